// round 13
// baseline (speedup 1.0000x reference)
#include <cuda_runtime.h>
#include <cuda_bf16.h>
#include <math.h>
#include <stdint.h>

#define NBATCH 16
#define LSEQ   4096
#define DIN    64
#define HCH    256
#define NST    32
#define NLAY   4
#define DOUT   10
#define SEG    512
#define NSEG   (LSEQ / SEG)

// ===========================================================================
// Base-ISA PTX helpers (compute_103 base — no tcgen05 / 'a'-suffix features)
// ===========================================================================
__device__ __forceinline__ uint32_t smem_u32(const void* p) {
    uint32_t a;
    asm("{ .reg .u64 t; cvta.to.shared.u64 t, %1; cvt.u32.u64 %0, t; }"
        : "=r"(a) : "l"(p));
    return a;
}
__device__ __forceinline__ void cp16(uint32_t dst, const void* src) {
    asm volatile("cp.async.cg.shared.global [%0], [%1], 16;"
                 :: "r"(dst), "l"(src));
}
#define CP_COMMIT() asm volatile("cp.async.commit_group;" ::: "memory")
#define CP_WAIT0()  asm volatile("cp.async.wait_group 0;" ::: "memory")
#define CP_WAIT1()  asm volatile("cp.async.wait_group 1;" ::: "memory")

__device__ __forceinline__ void ldsm4(uint32_t* r, uint32_t addr) {
    asm volatile("ldmatrix.sync.aligned.m8n8.x4.shared.b16 {%0,%1,%2,%3}, [%4];"
                 : "=r"(r[0]), "=r"(r[1]), "=r"(r[2]), "=r"(r[3]) : "r"(addr));
}
__device__ __forceinline__ void ldsm4t(uint32_t* r, uint32_t addr) {
    asm volatile("ldmatrix.sync.aligned.m8n8.x4.trans.shared.b16 {%0,%1,%2,%3}, [%4];"
                 : "=r"(r[0]), "=r"(r[1]), "=r"(r[2]), "=r"(r[3]) : "r"(addr));
}
__device__ __forceinline__ void mma_bf16(float* d, const uint32_t* a,
                                         uint32_t b0, uint32_t b1) {
    asm volatile(
        "mma.sync.aligned.m16n8k16.row.col.f32.bf16.bf16.f32 "
        "{%0,%1,%2,%3}, {%4,%5,%6,%7}, {%8,%9}, {%0,%1,%2,%3};"
        : "+f"(d[0]), "+f"(d[1]), "+f"(d[2]), "+f"(d[3])
        : "r"(a[0]), "r"(a[1]), "r"(a[2]), "r"(a[3]), "r"(b0), "r"(b1));
}

// ===========================================================================
// Packed fp32x2 helpers
// ===========================================================================
__device__ __forceinline__ unsigned long long pack2(float x, float y) {
    unsigned long long r;
    asm("mov.b64 %0, {%1, %2};" : "=l"(r) : "f"(x), "f"(y));
    return r;
}
__device__ __forceinline__ void fma2(unsigned long long& d,
                                     unsigned long long a,
                                     unsigned long long b) {
    asm("fma.rn.f32x2 %0, %1, %2, %0;" : "+l"(d) : "l"(a), "l"(b));
}
__device__ __forceinline__ void add2(unsigned long long& d,
                                     unsigned long long a) {
    asm("add.rn.f32x2 %0, %0, %1;" : "+l"(d) : "l"(a));
}
__device__ __forceinline__ float2 unpack2(unsigned long long v) {
    float2 r;
    asm("mov.b64 {%0, %1}, %2;" : "=f"(r.x), "=f"(r.y) : "l"(v));
    return r;
}

// ===========================================================================
// Device scratch
// ===========================================================================
__device__ float g_h[NBATCH * HCH * LSEQ];                       // (B,H,L)
__device__ __nv_bfloat16 g_yh[(size_t)NBATCH * HCH * LSEQ];      // y hi, [c][l]
__device__ __nv_bfloat16 g_yl[(size_t)NBATCH * HCH * LSEQ];      // y lo, [c][l]
__device__ __nv_bfloat16 g_wh[NLAY * 512 * HCH];                 // out_w hi
__device__ __nv_bfloat16 g_wl[NLAY * 512 * HCH];                 // out_w lo
__device__ float g_par[NLAY][6][HCH * NST];   // w, C-coefs, w^SEG
__device__ float2 g_e[NBATCH * HCH * NST * NSEG];   // segment end/init states

// ===========================================================================
// Prep: SSM parameter precompute (incl. w^SEG) + out_w bf16 hi/lo split.
// ===========================================================================
__global__ void prep_kernel(const float* __restrict__ log_dt,
                            const float* __restrict__ log_A_real,
                            const float* __restrict__ A_imag,
                            const float* __restrict__ C_re,
                            const float* __restrict__ C_im,
                            const float* __restrict__ out_w) {
    int idx = blockIdx.x * blockDim.x + threadIdx.x;
    if (idx < NLAY * 512 * HCH) {
        float w = out_w[idx];
        __nv_bfloat16 hi = __float2bfloat16(w);
        g_wh[idx] = hi;
        g_wl[idx] = __float2bfloat16(w - __bfloat162float(hi));
    }
    if (idx < NLAY * HCH * NST) {
        int layer = idx / (HCH * NST);
        int hn    = idx - layer * (HCH * NST);
        int h     = hn / NST;

        float dt  = expf(log_dt[layer * HCH + h]);
        float Are = -expf(log_A_real[idx]);
        float Aim = A_imag[idx];
        float dre = Are * dt;
        float dimg = Aim * dt;

        float sy, cy;
        sincosf(dimg, &sy, &cy);
        float em1 = expm1f(dre);
        float ex  = em1 + 1.0f;
        float wre = ex * cy;
        float wim = ex * sy;
        float emr = fmaf(em1, cy, cy - 1.0f);
        float emi = ex * sy;

        float inv = 1.0f / fmaf(Are, Are, Aim * Aim);
        float tre = fmaf(emr, Are, emi * Aim) * inv;
        float tim = fmaf(emi, Are, -emr * Aim) * inv;

        float cre = C_re[idx], cim = C_im[idx];
        float ctre = fmaf(cre, tre, -cim * tim);
        float ctim = fmaf(cre, tim, cim * tre);

        g_par[layer][0][hn] = wre;
        g_par[layer][1][hn] = wim;
        g_par[layer][2][hn] = 2.0f * ctre;
        g_par[layer][3][hn] = -2.0f * ctim;

        // w^SEG = exp(SEG * dt * A) — matches reference Vandermonde semantics
        float sp, cp;
        sincosf((float)SEG * dimg, &sp, &cp);
        float ep = expf((float)SEG * dre);
        g_par[layer][4][hn] = ep * cp;
        g_par[layer][5][hn] = ep * sp;
    }
}

// ===========================================================================
// Encoder
// ===========================================================================
__global__ void __launch_bounds__(256) encoder_kernel(
    const float* __restrict__ x,
    const float* __restrict__ enc_w,
    const float* __restrict__ enc_b) {
    extern __shared__ float sm[];
    float* Wsh = sm;               // [64][256]
    float* Xsh = sm + 64 * HCH;    // [64][68]

    int b    = blockIdx.y;
    int pos0 = blockIdx.x * 64;
    int tid  = threadIdx.x;

    {
        const float4* wrow = (const float4*)(enc_w + (size_t)tid * DIN);
#pragma unroll
        for (int q = 0; q < 16; q++) {
            float4 v = wrow[q];
            Wsh[(q * 4 + 0) * HCH + tid] = v.x;
            Wsh[(q * 4 + 1) * HCH + tid] = v.y;
            Wsh[(q * 4 + 2) * HCH + tid] = v.z;
            Wsh[(q * 4 + 3) * HCH + tid] = v.w;
        }
    }
    {
#pragma unroll
        for (int k = 0; k < 4; k++) {
            int e  = tid + k * 256;
            int l  = e >> 4;
            int i4 = e & 15;
            const float4* xr =
                (const float4*)(x + ((size_t)(b * LSEQ) + pos0 + l) * DIN);
            float4 v = xr[i4];
            Xsh[(i4 * 4 + 0) * 68 + l] = v.x;
            Xsh[(i4 * 4 + 1) * 68 + l] = v.y;
            Xsh[(i4 * 4 + 2) * 68 + l] = v.z;
            Xsh[(i4 * 4 + 3) * 68 + l] = v.w;
        }
    }
    __syncthreads();

    int th = tid >> 3;
    int tl = tid & 7;
    unsigned long long acc2[8][4];
#pragma unroll
    for (int r = 0; r < 8; r++)
#pragma unroll
        for (int c = 0; c < 4; c++) acc2[r][c] = 0ULL;

    for (int i = 0; i < DIN; i++) {
        float4 a0 = *(const float4*)&Wsh[i * HCH + th * 8];
        float4 a1 = *(const float4*)&Wsh[i * HCH + th * 8 + 4];
        ulonglong2 b0 = *(const ulonglong2*)&Xsh[i * 68 + tl * 8];
        ulonglong2 b1 = *(const ulonglong2*)&Xsh[i * 68 + tl * 8 + 4];
        unsigned long long bv[4] = {b0.x, b0.y, b1.x, b1.y};
        float av[8] = {a0.x, a0.y, a0.z, a0.w, a1.x, a1.y, a1.z, a1.w};
#pragma unroll
        for (int r = 0; r < 8; r++) {
            unsigned long long ar = pack2(av[r], av[r]);
#pragma unroll
            for (int c = 0; c < 4; c++) fma2(acc2[r][c], ar, bv[c]);
        }
    }

#pragma unroll
    for (int r = 0; r < 8; r++) {
        int h = th * 8 + r;
        float bias = __ldg(&enc_b[h]);
        float* dst = g_h + ((size_t)(b * HCH + h)) * LSEQ + pos0 + tl * 8;
        float2 p0 = unpack2(acc2[r][0]);
        float2 p1 = unpack2(acc2[r][1]);
        float2 p2 = unpack2(acc2[r][2]);
        float2 p3 = unpack2(acc2[r][3]);
        float4 o0 = make_float4(p0.x + bias, p0.y + bias, p1.x + bias, p1.y + bias);
        float4 o1 = make_float4(p2.x + bias, p2.y + bias, p3.x + bias, p3.y + bias);
        ((float4*)dst)[0] = o0;
        ((float4*)dst)[1] = o1;
    }
}

// ===========================================================================
// Segmented scan, pass A: per (channel, segment) warp, zero-init recurrence,
// store segment end state. No outputs — 4 fma + 1 shfl per step.
// ===========================================================================
__global__ void __launch_bounds__(128) scanA_kernel(int layer) {
    int tid  = threadIdx.x;
    int wid  = tid >> 5;
    int lane = tid & 31;
    int gw   = blockIdx.x * 4 + wid;
    int c    = gw >> 3;          // channel 0..4095
    int seg  = gw & 7;
    int h    = c & (HCH - 1);

    const float* par = &g_par[layer][0][0];
    float wre = par[0 * (HCH * NST) + h * NST + lane];
    float wim = par[1 * (HCH * NST) + h * NST + lane];

    const float* zin = g_h + (size_t)c * LSEQ + seg * SEG;

    float sre = 0.0f, sim = 0.0f;
    float zv = zin[lane];
    for (int l0 = 0; l0 < SEG; l0 += 32) {
        float zn = (l0 + 32 < SEG) ? zin[l0 + 32 + lane] : 0.0f;
#pragma unroll
        for (int t = 0; t < 32; t++) {
            float z  = __shfl_sync(0xffffffffu, zv, t);
            float nr = fmaf(wre, sre, z);
            nr       = fmaf(-wim, sim, nr);
            float ni = fmaf(wim, sre, wre * sim);
            sre = nr;
            sim = ni;
        }
        zv = zn;
    }
    g_e[((size_t)c * NST + lane) * NSEG + seg] = make_float2(sre, sim);
}

// ===========================================================================
// Segmented scan, pass B: propagate initial states across segments.
// s_init(0)=0; s_init(k) = w^SEG * s_init(k-1) + e(k-1). In-place in g_e.
// ===========================================================================
__global__ void __launch_bounds__(256) scanB_kernel(int layer) {
    int idx = blockIdx.x * blockDim.x + threadIdx.x;   // (c, n)
    if (idx >= NBATCH * HCH * NST) return;
    int c = idx >> 5;
    int n = idx & 31;
    int h = c & (HCH - 1);

    float wpre = g_par[layer][4][h * NST + n];
    float wpim = g_par[layer][5][h * NST + n];

    float2 e[NSEG];
#pragma unroll
    for (int k = 0; k < NSEG; k++) e[k] = g_e[(size_t)idx * NSEG + k];

    float sre = 0.0f, sim = 0.0f;
    float2 out[NSEG];
#pragma unroll
    for (int k = 0; k < NSEG; k++) {
        out[k] = make_float2(sre, sim);
        float nr = fmaf(wpre, sre, fmaf(-wpim, sim, e[k].x));
        float ni = fmaf(wpim, sre, fmaf(wpre, sim, e[k].y));
        sre = nr;
        sim = ni;
    }
#pragma unroll
    for (int k = 0; k < NSEG; k++) g_e[(size_t)idx * NSEG + k] = out[k];
}

// ===========================================================================
// Segmented scan, pass C: full output recurrence per segment from the
// propagated initial state. D-skip + GELU -> bf16 hi/lo, [c][l] layout.
// ===========================================================================
__global__ void __launch_bounds__(128) scanC_kernel(const float* __restrict__ Dvec,
                                                    int layer) {
    __shared__ float sh[4][32][36];
    int tid  = threadIdx.x;
    int wid  = tid >> 5;
    int lane = tid & 31;
    int gw   = blockIdx.x * 4 + wid;
    int c    = gw >> 3;
    int seg  = gw & 7;
    int h    = c & (HCH - 1);

    const float* par = &g_par[layer][0][0];
    float wre = par[0 * (HCH * NST) + h * NST + lane];
    float wim = par[1 * (HCH * NST) + h * NST + lane];
    float ca  = par[2 * (HCH * NST) + h * NST + lane];
    float cb  = par[3 * (HCH * NST) + h * NST + lane];
    float Dh  = __ldg(&Dvec[layer * HCH + h]);

    const float* zin = g_h + (size_t)c * LSEQ + seg * SEG;
    __nv_bfloat16* yh = g_yh + (size_t)c * LSEQ + seg * SEG;
    __nv_bfloat16* yl = g_yl + (size_t)c * LSEQ + seg * SEG;
    float (*S)[36] = sh[wid];

    float2 s0 = g_e[((size_t)c * NST + lane) * NSEG + seg];
    float sre = s0.x, sim = s0.y;
    float zv = zin[lane];
    for (int l0 = 0; l0 < SEG; l0 += 32) {
        float zn = (l0 + 32 < SEG) ? zin[l0 + 32 + lane] : 0.0f;
#pragma unroll
        for (int t = 0; t < 32; t++) {
            float z  = __shfl_sync(0xffffffffu, zv, t);
            float nr = fmaf(wre, sre, z);
            nr       = fmaf(-wim, sim, nr);
            float ni = fmaf(wim, sre, wre * sim);
            sre = nr;
            sim = ni;
            S[t][lane] = fmaf(ca, sre, cb * sim);
        }
        __syncwarp();
        unsigned long long a0 = 0ULL, a1 = 0ULL, a2 = 0ULL, a3 = 0ULL;
        const float* row = &S[lane][0];
#pragma unroll
        for (int q = 0; q < 8; q += 2) {
            ulonglong2 p0 = *(const ulonglong2*)(row + q * 4);
            ulonglong2 p1 = *(const ulonglong2*)(row + q * 4 + 4);
            add2(a0, p0.x);
            add2(a1, p0.y);
            add2(a2, p1.x);
            add2(a3, p1.y);
        }
        add2(a0, a2);
        add2(a1, a3);
        add2(a0, a1);
        float2 fr = unpack2(a0);
        float acc = fr.x + fr.y;

        float yv = fmaf(Dh, zv, acc);
        float u  = 0.7978845608028654f * fmaf(0.044715f, yv * yv * yv, yv);
        float gv = yv / (1.0f + __expf(-2.0f * u));
        __nv_bfloat16 bh = __float2bfloat16(gv);
        __nv_bfloat16 bl = __float2bfloat16(gv - __bfloat162float(bh));
        yh[l0 + lane] = bh;
        yl[l0 + lane] = bl;
        __syncwarp();
        zv = zn;
    }
}

// ===========================================================================
// FUSED: HMMA GEMM (bf16 3-term split, fp32 acc) + bias + GLU + residual +
// channel LayerNorm. 512 threads / 16 warps (R12 body verbatim).
// ===========================================================================
#define FA_STRIDE 144
#define FA_TILE   (32 * FA_STRIDE)                 // 4608
#define FB_STRIDE 80
#define FB_TILE   (512 * FB_STRIDE)                // 40960
#define F_AH      0
#define F_AL      FA_TILE
#define F_BH      (2 * FA_TILE)
#define F_BL      (2 * FA_TILE + FB_TILE)
#define F_BUF     (2 * FA_TILE + 2 * FB_TILE)      // 91136
#define FUSED_SMEM (2 * F_BUF)                     // 182272
#define EPI_G2    0                                // f32 [64][260]
#define EPI_RES   (64 * 260 * 4)                   // f32 [64][260]

__global__ void __launch_bounds__(512, 1) fused_glu_ln_kernel(
    const float* __restrict__ out_b, const float* __restrict__ ln_w,
    const float* __restrict__ ln_b, int layer) {
    extern __shared__ char smem[];
    __shared__ float s_ob[512];
    __shared__ float s_lnw[HCH];
    __shared__ float s_lnb[HCH];
    __shared__ float s_mu[64];
    __shared__ float s_rs[64];

    int tid  = threadIdx.x;
    int wid  = tid >> 5;
    int lane = tid & 31;
    int row0 = blockIdx.x * 64;           // position rows, in [0, B*L)
    int b    = row0 >> 12;
    int pos0 = row0 & (LSEQ - 1);

    s_ob[tid] = __ldg(&out_b[layer * 512 + tid]);
    if (tid < HCH) {
        s_lnw[tid] = __ldg(&ln_w[layer * HCH + tid]);
        s_lnb[tid] = __ldg(&ln_b[layer * HCH + tid]);
    }

    const __nv_bfloat16* Ah = g_yh + ((size_t)(b * HCH)) * LSEQ + pos0;
    const __nv_bfloat16* Al = g_yl + ((size_t)(b * HCH)) * LSEQ + pos0;
    const __nv_bfloat16* Bh = g_wh + (size_t)layer * 512 * HCH;
    const __nv_bfloat16* Bl = g_wl + (size_t)layer * 512 * HCH;

    uint32_t sb = smem_u32(smem);

    int a_kr  = tid >> 3;        // only tid<256 used (k-row 0..31)
    int a_seg = tid & 7;
    int b_jr0 = tid >> 2;        // 0..127 (then +128*i)
    int b_seg = tid & 3;

    float acc[16][4];
#pragma unroll
    for (int t = 0; t < 16; t++)
#pragma unroll
        for (int e = 0; e < 4; e++) acc[t][e] = 0.0f;

    int mt = wid >> 2;           // 0..3 (16-row group)
    int jq = wid & 3;            // 0..3 (128-j quarter)

    // stage chunk 0
    {
        uint32_t base = sb;
        if (tid < 256) {
            uint32_t d = base + a_kr * FA_STRIDE + a_seg * 16;
            size_t go = (size_t)a_kr * LSEQ + a_seg * 8;
            cp16(d + F_AH, Ah + go);
            cp16(d + F_AL, Al + go);
        }
#pragma unroll
        for (int i = 0; i < 4; i++) {
            int jr = b_jr0 + i * 128;
            uint32_t d = base + jr * FB_STRIDE + b_seg * 16;
            size_t go = (size_t)jr * HCH + b_seg * 8;
            cp16(d + F_BH, Bh + go);
            cp16(d + F_BL, Bl + go);
        }
        CP_COMMIT();
    }

    int f_kr = (lane & 7) + ((lane >> 4) << 3);
    int f_mc = ((lane >> 3) & 1) * 8;

    int buf = 0;
    for (int ch = 0; ch < 8; ch++) {
        if (ch < 7) {
            uint32_t base = sb + (buf ^ 1) * F_BUF;
            int k0 = (ch + 1) * 32;
            if (tid < 256) {
                uint32_t d = base + a_kr * FA_STRIDE + a_seg * 16;
                size_t go = (size_t)(k0 + a_kr) * LSEQ + a_seg * 8;
                cp16(d + F_AH, Ah + go);
                cp16(d + F_AL, Al + go);
            }
#pragma unroll
            for (int i = 0; i < 4; i++) {
                int jr = b_jr0 + i * 128;
                uint32_t d = base + jr * FB_STRIDE + b_seg * 16;
                size_t go = (size_t)jr * HCH + k0 + b_seg * 8;
                cp16(d + F_BH, Bh + go);
                cp16(d + F_BL, Bl + go);
            }
            CP_COMMIT();
            CP_WAIT1();
        } else {
            CP_WAIT0();
        }
        __syncthreads();

        uint32_t cbase = sb + buf * F_BUF;
#pragma unroll
        for (int pass = 0; pass < 3; pass++) {
            uint32_t aoff = cbase + (pass == 2 ? F_AL : F_AH);
            uint32_t boff = cbase + (pass == 1 ? F_BL : F_BH);
#pragma unroll
            for (int ks = 0; ks < 2; ks++) {
                uint32_t afrag[4];
                ldsm4t(afrag, aoff + (ks * 16 + f_kr) * FA_STRIDE +
                              (mt * 16 + f_mc) * 2);
#pragma unroll
                for (int grp = 0; grp < 2; grp++) {
                    uint32_t bfrag[4][4];
#pragma unroll
                    for (int gg = 0; gg < 4; gg++) {
                        int ng = grp * 4 + gg;
                        uint32_t ba = boff +
                            (jq * 128 + ng * 16 + (lane & 15)) * FB_STRIDE +
                            ks * 32 + (lane >> 4) * 16;
                        ldsm4(bfrag[gg], ba);
                    }
#pragma unroll
                    for (int gg = 0; gg < 4; gg++) {
                        int ng = grp * 4 + gg;
                        mma_bf16(acc[ng * 2],     afrag, bfrag[gg][0], bfrag[gg][2]);
                        mma_bf16(acc[ng * 2 + 1], afrag, bfrag[gg][1], bfrag[gg][3]);
                    }
                }
            }
        }
        __syncthreads();
        buf ^= 1;
    }

    // ---------------- fused epilogue (aliases tile smem) ----------------
    float* Gs2 = (float*)(smem + EPI_G2);    // [64][260]
    float* Rsm = (float*)(smem + EPI_RES);   // [64][260]

    {
        const float* resb = g_h + (size_t)(b * HCH) * LSEQ + pos0;
#pragma unroll
        for (int i = 0; i < 8; i++) {
            int flat = tid + i * 512;
            int h    = flat >> 4;
            int sg   = flat & 15;
            float4 v = *(const float4*)(resb + (size_t)h * LSEQ + sg * 4);
            Rsm[(sg * 4 + 0) * 260 + h] = v.x;
            Rsm[(sg * 4 + 1) * 260 + h] = v.y;
            Rsm[(sg * 4 + 2) * 260 + h] = v.z;
            Rsm[(sg * 4 + 3) * 260 + h] = v.w;
        }
    }
    if (jq >= 2) {
#pragma unroll
        for (int t = 0; t < 16; t++) {
            int j2 = (jq - 2) * 128 + (t >> 1) * 16 + (t & 1) * 8 + (lane & 3) * 2;
            int r  = mt * 16 + (lane >> 2);
            float bb0 = s_ob[256 + j2];
            float bb1 = s_ob[256 + j2 + 1];
            Gs2[r * 260 + j2]           = acc[t][0] + bb0;
            Gs2[r * 260 + j2 + 1]       = acc[t][1] + bb1;
            Gs2[(r + 8) * 260 + j2]     = acc[t][2] + bb0;
            Gs2[(r + 8) * 260 + j2 + 1] = acc[t][3] + bb1;
        }
    }
    __syncthreads();

    if (jq < 2) {
#pragma unroll
        for (int t = 0; t < 16; t++) {
            int h = jq * 128 + (t >> 1) * 16 + (t & 1) * 8 + (lane & 3) * 2;
            int r = mt * 16 + (lane >> 2);
            float bb0 = s_ob[h];
            float bb1 = s_ob[h + 1];
#pragma unroll
            for (int e = 0; e < 4; e++) {
                int rr = r + ((e >> 1) << 3);
                int hh = h + (e & 1);
                float g1 = acc[t][e] + ((e & 1) ? bb1 : bb0);
                float g2 = Gs2[rr * 260 + hh];
                float u  = fmaf(g1, 1.0f / (1.0f + __expf(-g2)),
                                Rsm[rr * 260 + hh]);
                Gs2[rr * 260 + hh] = u;
            }
        }
    }
    __syncthreads();

    {
        int r = tid >> 3;
        int q = tid & 7;
        float s = 0.0f, sq = 0.0f;
#pragma unroll
        for (int i = 0; i < 32; i++) {
            float v = Gs2[r * 260 + q * 32 + i];
            s += v;
            sq = fmaf(v, v, sq);
        }
        s  += __shfl_xor_sync(0xffffffffu, s, 1);
        sq += __shfl_xor_sync(0xffffffffu, sq, 1);
        s  += __shfl_xor_sync(0xffffffffu, s, 2);
        sq += __shfl_xor_sync(0xffffffffu, sq, 2);
        s  += __shfl_xor_sync(0xffffffffu, s, 4);
        sq += __shfl_xor_sync(0xffffffffu, sq, 4);
        if (q == 0) {
            float m = s * (1.0f / 256.0f);
            s_mu[r] = m;
            s_rs[r] = rsqrtf(fmaf(-m, m, sq * (1.0f / 256.0f)) + 1e-5f);
        }
    }
    __syncthreads();

    {
        int h    = tid & 255;
        int half = tid >> 8;
        float w  = s_lnw[h];
        float bb = s_lnb[h];
        float* outp = g_h + ((size_t)(b * HCH + h)) * LSEQ + pos0 + half * 32;
#pragma unroll
        for (int p4 = 0; p4 < 8; p4++) {
            int pp = half * 32 + p4 * 4;
            float4 o;
            float u0 = Gs2[(pp + 0) * 260 + h];
            float u1 = Gs2[(pp + 1) * 260 + h];
            float u2 = Gs2[(pp + 2) * 260 + h];
            float u3 = Gs2[(pp + 3) * 260 + h];
            o.x = fmaf((u0 - s_mu[pp + 0]) * s_rs[pp + 0], w, bb);
            o.y = fmaf((u1 - s_mu[pp + 1]) * s_rs[pp + 1], w, bb);
            o.z = fmaf((u2 - s_mu[pp + 2]) * s_rs[pp + 2], w, bb);
            o.w = fmaf((u3 - s_mu[pp + 3]) * s_rs[pp + 3], w, bb);
            *(float4*)(outp + p4 * 4) = o;
        }
    }
}

// ===========================================================================
// Decoder
// ===========================================================================
__global__ void __launch_bounds__(256) decoder_kernel(
    const float* __restrict__ dec_w, const float* __restrict__ dec_b,
    float* __restrict__ out) {
    __shared__ float wsh[DOUT * HCH];
    __shared__ float bsh[DOUT];
    int b    = blockIdx.y;
    int pos0 = blockIdx.x * 256;
    int tid  = threadIdx.x;
    for (int e = tid; e < DOUT * HCH; e += 256) wsh[e] = dec_w[e];
    if (tid < DOUT) bsh[tid] = dec_b[tid];
    __syncthreads();

    float acc[DOUT];
#pragma unroll
    for (int o = 0; o < DOUT; o++) acc[o] = bsh[o];

    const float* hp = g_h + (size_t)b * HCH * LSEQ + pos0 + tid;
    for (int h = 0; h < HCH; h++) {
        float xv = hp[(size_t)h * LSEQ];
#pragma unroll
        for (int o = 0; o < DOUT; o++)
            acc[o] = fmaf(xv, wsh[o * HCH + h], acc[o]);
    }
    float* op = out + ((size_t)(b * LSEQ) + pos0 + tid) * DOUT;
#pragma unroll
    for (int o = 0; o < DOUT; o++) op[o] = acc[o];
}

// ===========================================================================
extern "C" void kernel_launch(void* const* d_in, const int* in_sizes, int n_in,
                              void* d_out, int out_size) {
    const float* x          = (const float*)d_in[0];
    const float* enc_w      = (const float*)d_in[1];
    const float* enc_b      = (const float*)d_in[2];
    const float* log_dt     = (const float*)d_in[3];
    const float* log_A_real = (const float*)d_in[4];
    const float* A_imag     = (const float*)d_in[5];
    const float* C_re       = (const float*)d_in[6];
    const float* C_im       = (const float*)d_in[7];
    const float* Dv         = (const float*)d_in[8];
    const float* out_w      = (const float*)d_in[9];
    const float* out_b      = (const float*)d_in[10];
    const float* ln_w       = (const float*)d_in[11];
    const float* ln_b       = (const float*)d_in[12];
    const float* dec_w      = (const float*)d_in[13];
    const float* dec_b      = (const float*)d_in[14];
    float* out = (float*)d_out;

    size_t enc_smem = (size_t)(64 * HCH + 64 * 68) * sizeof(float);
    cudaFuncSetAttribute(encoder_kernel,
                         cudaFuncAttributeMaxDynamicSharedMemorySize,
                         (int)enc_smem);
    cudaFuncSetAttribute(fused_glu_ln_kernel,
                         cudaFuncAttributeMaxDynamicSharedMemorySize,
                         FUSED_SMEM);

    prep_kernel<<<(NLAY * 512 * HCH + 255) / 256, 256>>>(
        log_dt, log_A_real, A_imag, C_re, C_im, out_w);
    encoder_kernel<<<dim3(LSEQ / 64, NBATCH), 256, enc_smem>>>(x, enc_w, enc_b);
    for (int layer = 0; layer < NLAY; layer++) {
        scanA_kernel<<<NBATCH * HCH * NSEG / 4, 128>>>(layer);
        scanB_kernel<<<NBATCH * HCH * NST / 256, 256>>>(layer);
        scanC_kernel<<<NBATCH * HCH * NSEG / 4, 128>>>(Dv, layer);
        fused_glu_ln_kernel<<<NBATCH * LSEQ / 64, 512, FUSED_SMEM>>>(
            out_b, ln_w, ln_b, layer);
    }
    decoder_kernel<<<dim3(LSEQ / 256, NBATCH), 256>>>(dec_w, dec_b, out);
}

// round 14
// speedup vs baseline: 1.0855x; 1.0855x over previous
#include <cuda_runtime.h>
#include <cuda_bf16.h>
#include <math.h>
#include <stdint.h>

#define NBATCH 16
#define LSEQ   4096
#define DIN    64
#define HCH    256
#define NST    32
#define NLAY   4
#define DOUT   10

typedef unsigned long long ull;

// ===========================================================================
// Base-ISA PTX helpers (compute_103 base — no tcgen05 / 'a'-suffix features)
// ===========================================================================
__device__ __forceinline__ uint32_t smem_u32(const void* p) {
    uint32_t a;
    asm("{ .reg .u64 t; cvta.to.shared.u64 t, %1; cvt.u32.u64 %0, t; }"
        : "=r"(a) : "l"(p));
    return a;
}
__device__ __forceinline__ void cp16(uint32_t dst, const void* src) {
    asm volatile("cp.async.cg.shared.global [%0], [%1], 16;"
                 :: "r"(dst), "l"(src));
}
#define CP_COMMIT() asm volatile("cp.async.commit_group;" ::: "memory")
#define CP_WAIT0()  asm volatile("cp.async.wait_group 0;" ::: "memory")
#define CP_WAIT1()  asm volatile("cp.async.wait_group 1;" ::: "memory")

__device__ __forceinline__ void ldsm4(uint32_t* r, uint32_t addr) {
    asm volatile("ldmatrix.sync.aligned.m8n8.x4.shared.b16 {%0,%1,%2,%3}, [%4];"
                 : "=r"(r[0]), "=r"(r[1]), "=r"(r[2]), "=r"(r[3]) : "r"(addr));
}
__device__ __forceinline__ void ldsm4t(uint32_t* r, uint32_t addr) {
    asm volatile("ldmatrix.sync.aligned.m8n8.x4.trans.shared.b16 {%0,%1,%2,%3}, [%4];"
                 : "=r"(r[0]), "=r"(r[1]), "=r"(r[2]), "=r"(r[3]) : "r"(addr));
}
__device__ __forceinline__ void mma_bf16(float* d, const uint32_t* a,
                                         uint32_t b0, uint32_t b1) {
    asm volatile(
        "mma.sync.aligned.m16n8k16.row.col.f32.bf16.bf16.f32 "
        "{%0,%1,%2,%3}, {%4,%5,%6,%7}, {%8,%9}, {%0,%1,%2,%3};"
        : "+f"(d[0]), "+f"(d[1]), "+f"(d[2]), "+f"(d[3])
        : "r"(a[0]), "r"(a[1]), "r"(a[2]), "r"(a[3]), "r"(b0), "r"(b1));
}

// ===========================================================================
// Packed fp32x2 helpers
// ===========================================================================
__device__ __forceinline__ ull pack2(float x, float y) {
    ull r;
    asm("mov.b64 %0, {%1, %2};" : "=l"(r) : "f"(x), "f"(y));
    return r;
}
__device__ __forceinline__ void fma2(ull& d, ull a, ull b) {
    asm("fma.rn.f32x2 %0, %1, %2, %0;" : "+l"(d) : "l"(a), "l"(b));
}
__device__ __forceinline__ ull mul2v(ull a, ull b) {
    ull r;
    asm("mul.rn.f32x2 %0, %1, %2;" : "=l"(r) : "l"(a), "l"(b));
    return r;
}
__device__ __forceinline__ void add2(ull& d, ull a) {
    asm("add.rn.f32x2 %0, %0, %1;" : "+l"(d) : "l"(a));
}
__device__ __forceinline__ float2 unpack2(ull v) {
    float2 r;
    asm("mov.b64 {%0, %1}, %2;" : "=f"(r.x), "=f"(r.y) : "l"(v));
    return r;
}

// ===========================================================================
// Device scratch
// ===========================================================================
__device__ float g_h[NBATCH * HCH * LSEQ];                       // (B,H,L)
__device__ __nv_bfloat16 g_yh[(size_t)NBATCH * HCH * LSEQ];      // y hi, [c][l]
__device__ __nv_bfloat16 g_yl[(size_t)NBATCH * HCH * LSEQ];      // y lo, [c][l]
__device__ __nv_bfloat16 g_wh[NLAY * 512 * HCH];                 // out_w hi
__device__ __nv_bfloat16 g_wl[NLAY * 512 * HCH];                 // out_w lo
__device__ float g_par[NLAY][4][HCH * NST];

// ===========================================================================
// Prep: SSM parameter precompute + out_w bf16 hi/lo split (merged).
// ===========================================================================
__global__ void prep_kernel(const float* __restrict__ log_dt,
                            const float* __restrict__ log_A_real,
                            const float* __restrict__ A_imag,
                            const float* __restrict__ C_re,
                            const float* __restrict__ C_im,
                            const float* __restrict__ out_w) {
    int idx = blockIdx.x * blockDim.x + threadIdx.x;
    if (idx < NLAY * 512 * HCH) {
        float w = out_w[idx];
        __nv_bfloat16 hi = __float2bfloat16(w);
        g_wh[idx] = hi;
        g_wl[idx] = __float2bfloat16(w - __bfloat162float(hi));
    }
    if (idx < NLAY * HCH * NST) {
        int layer = idx / (HCH * NST);
        int hn    = idx - layer * (HCH * NST);
        int h     = hn / NST;

        float dt  = expf(log_dt[layer * HCH + h]);
        float Are = -expf(log_A_real[idx]);
        float Aim = A_imag[idx];
        float dre = Are * dt;
        float dimg = Aim * dt;

        float sy, cy;
        sincosf(dimg, &sy, &cy);
        float em1 = expm1f(dre);
        float ex  = em1 + 1.0f;
        float wre = ex * cy;
        float wim = ex * sy;
        float emr = fmaf(em1, cy, cy - 1.0f);
        float emi = ex * sy;

        float inv = 1.0f / fmaf(Are, Are, Aim * Aim);
        float tre = fmaf(emr, Are, emi * Aim) * inv;
        float tim = fmaf(emi, Are, -emr * Aim) * inv;

        float cre = C_re[idx], cim = C_im[idx];
        float ctre = fmaf(cre, tre, -cim * tim);
        float ctim = fmaf(cre, tim, cim * tre);

        g_par[layer][0][hn] = wre;
        g_par[layer][1][hn] = wim;
        g_par[layer][2][hn] = 2.0f * ctre;
        g_par[layer][3][hn] = -2.0f * ctim;
    }
}

// ===========================================================================
// Encoder
// ===========================================================================
__global__ void __launch_bounds__(256) encoder_kernel(
    const float* __restrict__ x,
    const float* __restrict__ enc_w,
    const float* __restrict__ enc_b) {
    extern __shared__ float sm[];
    float* Wsh = sm;               // [64][256]
    float* Xsh = sm + 64 * HCH;    // [64][68]

    int b    = blockIdx.y;
    int pos0 = blockIdx.x * 64;
    int tid  = threadIdx.x;

    {
        const float4* wrow = (const float4*)(enc_w + (size_t)tid * DIN);
#pragma unroll
        for (int q = 0; q < 16; q++) {
            float4 v = wrow[q];
            Wsh[(q * 4 + 0) * HCH + tid] = v.x;
            Wsh[(q * 4 + 1) * HCH + tid] = v.y;
            Wsh[(q * 4 + 2) * HCH + tid] = v.z;
            Wsh[(q * 4 + 3) * HCH + tid] = v.w;
        }
    }
    {
#pragma unroll
        for (int k = 0; k < 4; k++) {
            int e  = tid + k * 256;
            int l  = e >> 4;
            int i4 = e & 15;
            const float4* xr =
                (const float4*)(x + ((size_t)(b * LSEQ) + pos0 + l) * DIN);
            float4 v = xr[i4];
            Xsh[(i4 * 4 + 0) * 68 + l] = v.x;
            Xsh[(i4 * 4 + 1) * 68 + l] = v.y;
            Xsh[(i4 * 4 + 2) * 68 + l] = v.z;
            Xsh[(i4 * 4 + 3) * 68 + l] = v.w;
        }
    }
    __syncthreads();

    int th = tid >> 3;
    int tl = tid & 7;
    ull acc2[8][4];
#pragma unroll
    for (int r = 0; r < 8; r++)
#pragma unroll
        for (int c = 0; c < 4; c++) acc2[r][c] = 0ULL;

    for (int i = 0; i < DIN; i++) {
        float4 a0 = *(const float4*)&Wsh[i * HCH + th * 8];
        float4 a1 = *(const float4*)&Wsh[i * HCH + th * 8 + 4];
        ulonglong2 b0 = *(const ulonglong2*)&Xsh[i * 68 + tl * 8];
        ulonglong2 b1 = *(const ulonglong2*)&Xsh[i * 68 + tl * 8 + 4];
        ull bv[4] = {b0.x, b0.y, b1.x, b1.y};
        float av[8] = {a0.x, a0.y, a0.z, a0.w, a1.x, a1.y, a1.z, a1.w};
#pragma unroll
        for (int r = 0; r < 8; r++) {
            ull ar = pack2(av[r], av[r]);
#pragma unroll
            for (int c = 0; c < 4; c++) fma2(acc2[r][c], ar, bv[c]);
        }
    }

#pragma unroll
    for (int r = 0; r < 8; r++) {
        int h = th * 8 + r;
        float bias = __ldg(&enc_b[h]);
        float* dst = g_h + ((size_t)(b * HCH + h)) * LSEQ + pos0 + tl * 8;
        float2 p0 = unpack2(acc2[r][0]);
        float2 p1 = unpack2(acc2[r][1]);
        float2 p2 = unpack2(acc2[r][2]);
        float2 p3 = unpack2(acc2[r][3]);
        float4 o0 = make_float4(p0.x + bias, p0.y + bias, p1.x + bias, p1.y + bias);
        float4 o1 = make_float4(p2.x + bias, p2.y + bias, p3.x + bias, p3.y + bias);
        ((float4*)dst)[0] = o0;
        ((float4*)dst)[1] = o1;
    }
}

// ===========================================================================
// SSM scan + D-skip + GELU -> bf16 hi/lo, [c][l] layout.
// CHANNEL-PAIR PACKED: one warp processes channels (2g, 2g+1) simultaneously;
// every recurrence/output op is fma.rn.f32x2 / mul.rn.f32x2 across the pair.
// Identical per-channel math to R12; ~30% fewer instructions per channel.
// 2048 warps -> 512 blocks x 128 thr, all resident in one wave (34KB smem).
// ===========================================================================
__global__ void __launch_bounds__(128) scan_kernel(const float* __restrict__ Dvec,
                                                   int layer) {
    __shared__ ull Ssh[4][32][34];
    int tid  = threadIdx.x;
    int wid  = tid >> 5;
    int lane = tid & 31;
    int cp   = blockIdx.x * 4 + wid;      // channel-pair 0..2047
    int c0   = cp * 2;
    int h0   = c0 & (HCH - 1);            // even; h1 = h0+1, same batch

    const float* par = &g_par[layer][0][0];
#define PP(k, hh) par[(k) * (HCH * NST) + (hh) * NST + lane]
    ull wre2  = pack2(PP(0, h0), PP(0, h0 + 1));
    ull wim2  = pack2(PP(1, h0), PP(1, h0 + 1));
    ull nwim2 = pack2(-PP(1, h0), -PP(1, h0 + 1));
    ull ca2   = pack2(PP(2, h0), PP(2, h0 + 1));
    ull cb2   = pack2(PP(3, h0), PP(3, h0 + 1));
#undef PP
    float D0 = __ldg(&Dvec[layer * HCH + h0]);
    float D1 = __ldg(&Dvec[layer * HCH + h0 + 1]);

    const float* z0p = g_h + (size_t)c0 * LSEQ;
    const float* z1p = z0p + LSEQ;
    __nv_bfloat16* yh0 = g_yh + (size_t)c0 * LSEQ;
    __nv_bfloat16* yl0 = g_yl + (size_t)c0 * LSEQ;
    __nv_bfloat16* yh1 = yh0 + LSEQ;
    __nv_bfloat16* yl1 = yl0 + LSEQ;
    ull (*S)[34] = Ssh[wid];

    ull sre2 = 0ULL, sim2 = 0ULL;
    float zv0 = z0p[lane];
    float zv1 = z1p[lane];
    for (int l0 = 0; l0 < LSEQ; l0 += 32) {
        float zn0 = (l0 + 32 < LSEQ) ? z0p[l0 + 32 + lane] : 0.0f;
        float zn1 = (l0 + 32 < LSEQ) ? z1p[l0 + 32 + lane] : 0.0f;
#pragma unroll
        for (int t = 0; t < 32; t++) {
            float za = __shfl_sync(0xffffffffu, zv0, t);
            float zb = __shfl_sync(0xffffffffu, zv1, t);
            ull nr = pack2(za, zb);
            fma2(nr, nwim2, sim2);        // nr = -wim*sim + z
            fma2(nr, wre2, sre2);         // nr += wre*sre
            ull ni = mul2v(wim2, sre2);
            fma2(ni, wre2, sim2);         // ni = wre*sim + wim*sre
            sre2 = nr;
            sim2 = ni;
            ull o = mul2v(cb2, sim2);
            fma2(o, ca2, sre2);           // o = ca*sre + cb*sim
            S[t][lane] = o;
        }
        __syncwarp();
        // lane t sums its row over n (packed across the channel pair)
        ull a0 = 0ULL, a1 = 0ULL, a2 = 0ULL, a3 = 0ULL;
        const ulonglong2* row = (const ulonglong2*)&S[lane][0];
#pragma unroll
        for (int q = 0; q < 16; q += 4) {
            ulonglong2 p0 = row[q];
            ulonglong2 p1 = row[q + 1];
            ulonglong2 p2 = row[q + 2];
            ulonglong2 p3 = row[q + 3];
            add2(a0, p0.x); add2(a0, p0.y);
            add2(a1, p1.x); add2(a1, p1.y);
            add2(a2, p2.x); add2(a2, p2.y);
            add2(a3, p3.x); add2(a3, p3.y);
        }
        add2(a0, a1);
        add2(a2, a3);
        add2(a0, a2);
        float2 s = unpack2(a0);

        float yv0 = fmaf(D0, zv0, s.x);
        float yv1 = fmaf(D1, zv1, s.y);
        float u0 = 0.7978845608028654f * fmaf(0.044715f, yv0 * yv0 * yv0, yv0);
        float u1 = 0.7978845608028654f * fmaf(0.044715f, yv1 * yv1 * yv1, yv1);
        float gv0 = yv0 / (1.0f + __expf(-2.0f * u0));
        float gv1 = yv1 / (1.0f + __expf(-2.0f * u1));
        __nv_bfloat16 bh0 = __float2bfloat16(gv0);
        __nv_bfloat16 bl0 = __float2bfloat16(gv0 - __bfloat162float(bh0));
        __nv_bfloat16 bh1 = __float2bfloat16(gv1);
        __nv_bfloat16 bl1 = __float2bfloat16(gv1 - __bfloat162float(bh1));
        yh0[l0 + lane] = bh0;
        yl0[l0 + lane] = bl0;
        yh1[l0 + lane] = bh1;
        yl1[l0 + lane] = bl1;
        __syncwarp();
        zv0 = zn0;
        zv1 = zn1;
    }
}

// ===========================================================================
// FUSED: HMMA GEMM (bf16 3-term split, fp32 acc) + bias + GLU + residual +
// channel LayerNorm. 512 threads / 16 warps (R12 body verbatim).
// ===========================================================================
#define FA_STRIDE 144
#define FA_TILE   (32 * FA_STRIDE)                 // 4608
#define FB_STRIDE 80
#define FB_TILE   (512 * FB_STRIDE)                // 40960
#define F_AH      0
#define F_AL      FA_TILE
#define F_BH      (2 * FA_TILE)
#define F_BL      (2 * FA_TILE + FB_TILE)
#define F_BUF     (2 * FA_TILE + 2 * FB_TILE)      // 91136
#define FUSED_SMEM (2 * F_BUF)                     // 182272
#define EPI_G2    0                                // f32 [64][260]
#define EPI_RES   (64 * 260 * 4)                   // f32 [64][260]

__global__ void __launch_bounds__(512, 1) fused_glu_ln_kernel(
    const float* __restrict__ out_b, const float* __restrict__ ln_w,
    const float* __restrict__ ln_b, int layer) {
    extern __shared__ char smem[];
    __shared__ float s_ob[512];
    __shared__ float s_lnw[HCH];
    __shared__ float s_lnb[HCH];
    __shared__ float s_mu[64];
    __shared__ float s_rs[64];

    int tid  = threadIdx.x;
    int wid  = tid >> 5;
    int lane = tid & 31;
    int row0 = blockIdx.x * 64;           // position rows, in [0, B*L)
    int b    = row0 >> 12;
    int pos0 = row0 & (LSEQ - 1);

    s_ob[tid] = __ldg(&out_b[layer * 512 + tid]);
    if (tid < HCH) {
        s_lnw[tid] = __ldg(&ln_w[layer * HCH + tid]);
        s_lnb[tid] = __ldg(&ln_b[layer * HCH + tid]);
    }

    const __nv_bfloat16* Ah = g_yh + ((size_t)(b * HCH)) * LSEQ + pos0;
    const __nv_bfloat16* Al = g_yl + ((size_t)(b * HCH)) * LSEQ + pos0;
    const __nv_bfloat16* Bh = g_wh + (size_t)layer * 512 * HCH;
    const __nv_bfloat16* Bl = g_wl + (size_t)layer * 512 * HCH;

    uint32_t sb = smem_u32(smem);

    int a_kr  = tid >> 3;        // only tid<256 used (k-row 0..31)
    int a_seg = tid & 7;
    int b_jr0 = tid >> 2;        // 0..127 (then +128*i)
    int b_seg = tid & 3;

    float acc[16][4];
#pragma unroll
    for (int t = 0; t < 16; t++)
#pragma unroll
        for (int e = 0; e < 4; e++) acc[t][e] = 0.0f;

    int mt = wid >> 2;           // 0..3 (16-row group)
    int jq = wid & 3;            // 0..3 (128-j quarter)

    // stage chunk 0
    {
        uint32_t base = sb;
        if (tid < 256) {
            uint32_t d = base + a_kr * FA_STRIDE + a_seg * 16;
            size_t go = (size_t)a_kr * LSEQ + a_seg * 8;
            cp16(d + F_AH, Ah + go);
            cp16(d + F_AL, Al + go);
        }
#pragma unroll
        for (int i = 0; i < 4; i++) {
            int jr = b_jr0 + i * 128;
            uint32_t d = base + jr * FB_STRIDE + b_seg * 16;
            size_t go = (size_t)jr * HCH + b_seg * 8;
            cp16(d + F_BH, Bh + go);
            cp16(d + F_BL, Bl + go);
        }
        CP_COMMIT();
    }

    int f_kr = (lane & 7) + ((lane >> 4) << 3);
    int f_mc = ((lane >> 3) & 1) * 8;

    int buf = 0;
    for (int ch = 0; ch < 8; ch++) {
        if (ch < 7) {
            uint32_t base = sb + (buf ^ 1) * F_BUF;
            int k0 = (ch + 1) * 32;
            if (tid < 256) {
                uint32_t d = base + a_kr * FA_STRIDE + a_seg * 16;
                size_t go = (size_t)(k0 + a_kr) * LSEQ + a_seg * 8;
                cp16(d + F_AH, Ah + go);
                cp16(d + F_AL, Al + go);
            }
#pragma unroll
            for (int i = 0; i < 4; i++) {
                int jr = b_jr0 + i * 128;
                uint32_t d = base + jr * FB_STRIDE + b_seg * 16;
                size_t go = (size_t)jr * HCH + k0 + b_seg * 8;
                cp16(d + F_BH, Bh + go);
                cp16(d + F_BL, Bl + go);
            }
            CP_COMMIT();
            CP_WAIT1();
        } else {
            CP_WAIT0();
        }
        __syncthreads();

        uint32_t cbase = sb + buf * F_BUF;
#pragma unroll
        for (int pass = 0; pass < 3; pass++) {
            uint32_t aoff = cbase + (pass == 2 ? F_AL : F_AH);
            uint32_t boff = cbase + (pass == 1 ? F_BL : F_BH);
#pragma unroll
            for (int ks = 0; ks < 2; ks++) {
                uint32_t afrag[4];
                ldsm4t(afrag, aoff + (ks * 16 + f_kr) * FA_STRIDE +
                              (mt * 16 + f_mc) * 2);
#pragma unroll
                for (int grp = 0; grp < 2; grp++) {
                    uint32_t bfrag[4][4];
#pragma unroll
                    for (int gg = 0; gg < 4; gg++) {
                        int ng = grp * 4 + gg;
                        uint32_t ba = boff +
                            (jq * 128 + ng * 16 + (lane & 15)) * FB_STRIDE +
                            ks * 32 + (lane >> 4) * 16;
                        ldsm4(bfrag[gg], ba);
                    }
#pragma unroll
                    for (int gg = 0; gg < 4; gg++) {
                        int ng = grp * 4 + gg;
                        mma_bf16(acc[ng * 2],     afrag, bfrag[gg][0], bfrag[gg][2]);
                        mma_bf16(acc[ng * 2 + 1], afrag, bfrag[gg][1], bfrag[gg][3]);
                    }
                }
            }
        }
        __syncthreads();
        buf ^= 1;
    }

    // ---------------- fused epilogue (aliases tile smem) ----------------
    float* Gs2 = (float*)(smem + EPI_G2);    // [64][260]
    float* Rsm = (float*)(smem + EPI_RES);   // [64][260]

    {
        const float* resb = g_h + (size_t)(b * HCH) * LSEQ + pos0;
#pragma unroll
        for (int i = 0; i < 8; i++) {
            int flat = tid + i * 512;
            int h    = flat >> 4;
            int sg   = flat & 15;
            float4 v = *(const float4*)(resb + (size_t)h * LSEQ + sg * 4);
            Rsm[(sg * 4 + 0) * 260 + h] = v.x;
            Rsm[(sg * 4 + 1) * 260 + h] = v.y;
            Rsm[(sg * 4 + 2) * 260 + h] = v.z;
            Rsm[(sg * 4 + 3) * 260 + h] = v.w;
        }
    }
    if (jq >= 2) {
#pragma unroll
        for (int t = 0; t < 16; t++) {
            int j2 = (jq - 2) * 128 + (t >> 1) * 16 + (t & 1) * 8 + (lane & 3) * 2;
            int r  = mt * 16 + (lane >> 2);
            float bb0 = s_ob[256 + j2];
            float bb1 = s_ob[256 + j2 + 1];
            Gs2[r * 260 + j2]           = acc[t][0] + bb0;
            Gs2[r * 260 + j2 + 1]       = acc[t][1] + bb1;
            Gs2[(r + 8) * 260 + j2]     = acc[t][2] + bb0;
            Gs2[(r + 8) * 260 + j2 + 1] = acc[t][3] + bb1;
        }
    }
    __syncthreads();

    if (jq < 2) {
#pragma unroll
        for (int t = 0; t < 16; t++) {
            int h = jq * 128 + (t >> 1) * 16 + (t & 1) * 8 + (lane & 3) * 2;
            int r = mt * 16 + (lane >> 2);
            float bb0 = s_ob[h];
            float bb1 = s_ob[h + 1];
#pragma unroll
            for (int e = 0; e < 4; e++) {
                int rr = r + ((e >> 1) << 3);
                int hh = h + (e & 1);
                float g1 = acc[t][e] + ((e & 1) ? bb1 : bb0);
                float g2 = Gs2[rr * 260 + hh];
                float u  = fmaf(g1, 1.0f / (1.0f + __expf(-g2)),
                                Rsm[rr * 260 + hh]);
                Gs2[rr * 260 + hh] = u;
            }
        }
    }
    __syncthreads();

    {
        int r = tid >> 3;
        int q = tid & 7;
        float s = 0.0f, sq = 0.0f;
#pragma unroll
        for (int i = 0; i < 32; i++) {
            float v = Gs2[r * 260 + q * 32 + i];
            s += v;
            sq = fmaf(v, v, sq);
        }
        s  += __shfl_xor_sync(0xffffffffu, s, 1);
        sq += __shfl_xor_sync(0xffffffffu, sq, 1);
        s  += __shfl_xor_sync(0xffffffffu, s, 2);
        sq += __shfl_xor_sync(0xffffffffu, sq, 2);
        s  += __shfl_xor_sync(0xffffffffu, s, 4);
        sq += __shfl_xor_sync(0xffffffffu, sq, 4);
        if (q == 0) {
            float m = s * (1.0f / 256.0f);
            s_mu[r] = m;
            s_rs[r] = rsqrtf(fmaf(-m, m, sq * (1.0f / 256.0f)) + 1e-5f);
        }
    }
    __syncthreads();

    {
        int h    = tid & 255;
        int half = tid >> 8;
        float w  = s_lnw[h];
        float bb = s_lnb[h];
        float* outp = g_h + ((size_t)(b * HCH + h)) * LSEQ + pos0 + half * 32;
#pragma unroll
        for (int p4 = 0; p4 < 8; p4++) {
            int pp = half * 32 + p4 * 4;
            float4 o;
            float u0 = Gs2[(pp + 0) * 260 + h];
            float u1 = Gs2[(pp + 1) * 260 + h];
            float u2 = Gs2[(pp + 2) * 260 + h];
            float u3 = Gs2[(pp + 3) * 260 + h];
            o.x = fmaf((u0 - s_mu[pp + 0]) * s_rs[pp + 0], w, bb);
            o.y = fmaf((u1 - s_mu[pp + 1]) * s_rs[pp + 1], w, bb);
            o.z = fmaf((u2 - s_mu[pp + 2]) * s_rs[pp + 2], w, bb);
            o.w = fmaf((u3 - s_mu[pp + 3]) * s_rs[pp + 3], w, bb);
            *(float4*)(outp + p4 * 4) = o;
        }
    }
}

// ===========================================================================
// Decoder
// ===========================================================================
__global__ void __launch_bounds__(256) decoder_kernel(
    const float* __restrict__ dec_w, const float* __restrict__ dec_b,
    float* __restrict__ out) {
    __shared__ float wsh[DOUT * HCH];
    __shared__ float bsh[DOUT];
    int b    = blockIdx.y;
    int pos0 = blockIdx.x * 256;
    int tid  = threadIdx.x;
    for (int e = tid; e < DOUT * HCH; e += 256) wsh[e] = dec_w[e];
    if (tid < DOUT) bsh[tid] = dec_b[tid];
    __syncthreads();

    float acc[DOUT];
#pragma unroll
    for (int o = 0; o < DOUT; o++) acc[o] = bsh[o];

    const float* hp = g_h + (size_t)b * HCH * LSEQ + pos0 + tid;
    for (int h = 0; h < HCH; h++) {
        float xv = hp[(size_t)h * LSEQ];
#pragma unroll
        for (int o = 0; o < DOUT; o++)
            acc[o] = fmaf(xv, wsh[o * HCH + h], acc[o]);
    }
    float* op = out + ((size_t)(b * LSEQ) + pos0 + tid) * DOUT;
#pragma unroll
    for (int o = 0; o < DOUT; o++) op[o] = acc[o];
}

// ===========================================================================
extern "C" void kernel_launch(void* const* d_in, const int* in_sizes, int n_in,
                              void* d_out, int out_size) {
    const float* x          = (const float*)d_in[0];
    const float* enc_w      = (const float*)d_in[1];
    const float* enc_b      = (const float*)d_in[2];
    const float* log_dt     = (const float*)d_in[3];
    const float* log_A_real = (const float*)d_in[4];
    const float* A_imag     = (const float*)d_in[5];
    const float* C_re       = (const float*)d_in[6];
    const float* C_im       = (const float*)d_in[7];
    const float* Dv         = (const float*)d_in[8];
    const float* out_w      = (const float*)d_in[9];
    const float* out_b      = (const float*)d_in[10];
    const float* ln_w       = (const float*)d_in[11];
    const float* ln_b       = (const float*)d_in[12];
    const float* dec_w      = (const float*)d_in[13];
    const float* dec_b      = (const float*)d_in[14];
    float* out = (float*)d_out;

    size_t enc_smem = (size_t)(64 * HCH + 64 * 68) * sizeof(float);
    cudaFuncSetAttribute(encoder_kernel,
                         cudaFuncAttributeMaxDynamicSharedMemorySize,
                         (int)enc_smem);
    cudaFuncSetAttribute(fused_glu_ln_kernel,
                         cudaFuncAttributeMaxDynamicSharedMemorySize,
                         FUSED_SMEM);

    prep_kernel<<<(NLAY * 512 * HCH + 255) / 256, 256>>>(
        log_dt, log_A_real, A_imag, C_re, C_im, out_w);
    encoder_kernel<<<dim3(LSEQ / 64, NBATCH), 256, enc_smem>>>(x, enc_w, enc_b);
    for (int layer = 0; layer < NLAY; layer++) {
        scan_kernel<<<NBATCH * HCH / 8, 128>>>(Dv, layer);
        fused_glu_ln_kernel<<<NBATCH * LSEQ / 64, 512, FUSED_SMEM>>>(
            out_b, ln_w, ln_b, layer);
    }
    decoder_kernel<<<dim3(LSEQ / 256, NBATCH), 256>>>(dec_w, dec_b, out);
}

// round 15
// speedup vs baseline: 1.1056x; 1.0185x over previous
#include <cuda_runtime.h>
#include <cuda_bf16.h>
#include <math.h>
#include <stdint.h>

#define NBATCH 16
#define LSEQ   4096
#define DIN    64
#define HCH    256
#define NST    32
#define NLAY   4
#define DOUT   10

typedef unsigned long long ull;

// ===========================================================================
// Base-ISA PTX helpers (compute_103 base — no tcgen05 / 'a'-suffix features)
// ===========================================================================
__device__ __forceinline__ uint32_t smem_u32(const void* p) {
    uint32_t a;
    asm("{ .reg .u64 t; cvta.to.shared.u64 t, %1; cvt.u32.u64 %0, t; }"
        : "=r"(a) : "l"(p));
    return a;
}
__device__ __forceinline__ void cp16(uint32_t dst, const void* src) {
    asm volatile("cp.async.cg.shared.global [%0], [%1], 16;"
                 :: "r"(dst), "l"(src));
}
#define CP_COMMIT() asm volatile("cp.async.commit_group;" ::: "memory")
#define CP_WAIT0()  asm volatile("cp.async.wait_group 0;" ::: "memory")
#define CP_WAIT1()  asm volatile("cp.async.wait_group 1;" ::: "memory")

__device__ __forceinline__ void ldsm4(uint32_t* r, uint32_t addr) {
    asm volatile("ldmatrix.sync.aligned.m8n8.x4.shared.b16 {%0,%1,%2,%3}, [%4];"
                 : "=r"(r[0]), "=r"(r[1]), "=r"(r[2]), "=r"(r[3]) : "r"(addr));
}
__device__ __forceinline__ void ldsm4t(uint32_t* r, uint32_t addr) {
    asm volatile("ldmatrix.sync.aligned.m8n8.x4.trans.shared.b16 {%0,%1,%2,%3}, [%4];"
                 : "=r"(r[0]), "=r"(r[1]), "=r"(r[2]), "=r"(r[3]) : "r"(addr));
}
__device__ __forceinline__ void mma_bf16(float* d, const uint32_t* a,
                                         uint32_t b0, uint32_t b1) {
    asm volatile(
        "mma.sync.aligned.m16n8k16.row.col.f32.bf16.bf16.f32 "
        "{%0,%1,%2,%3}, {%4,%5,%6,%7}, {%8,%9}, {%0,%1,%2,%3};"
        : "+f"(d[0]), "+f"(d[1]), "+f"(d[2]), "+f"(d[3])
        : "r"(a[0]), "r"(a[1]), "r"(a[2]), "r"(a[3]), "r"(b0), "r"(b1));
}

// ===========================================================================
// Packed fp32x2 helpers
// ===========================================================================
__device__ __forceinline__ ull pack2(float x, float y) {
    ull r;
    asm("mov.b64 %0, {%1, %2};" : "=l"(r) : "f"(x), "f"(y));
    return r;
}
__device__ __forceinline__ void fma2(ull& d, ull a, ull b) {
    asm("fma.rn.f32x2 %0, %1, %2, %0;" : "+l"(d) : "l"(a), "l"(b));
}
__device__ __forceinline__ void add2(ull& d, ull a) {
    asm("add.rn.f32x2 %0, %0, %1;" : "+l"(d) : "l"(a));
}
__device__ __forceinline__ float2 unpack2(ull v) {
    float2 r;
    asm("mov.b64 {%0, %1}, %2;" : "=f"(r.x), "=f"(r.y) : "l"(v));
    return r;
}

// ===========================================================================
// Device scratch
// ===========================================================================
__device__ float g_h[NBATCH * HCH * LSEQ];                       // (B,H,L)
__device__ __nv_bfloat16 g_yh[(size_t)NBATCH * HCH * LSEQ];      // y hi, [c][l]
__device__ __nv_bfloat16 g_yl[(size_t)NBATCH * HCH * LSEQ];      // y lo, [c][l]
__device__ __nv_bfloat16 g_wh[NLAY * 512 * HCH];                 // out_w hi
__device__ __nv_bfloat16 g_wl[NLAY * 512 * HCH];                 // out_w lo
__device__ float g_par[NLAY][4][HCH * NST];

// ===========================================================================
// Prep: SSM parameter precompute + out_w bf16 hi/lo split (merged).
// ===========================================================================
__global__ void prep_kernel(const float* __restrict__ log_dt,
                            const float* __restrict__ log_A_real,
                            const float* __restrict__ A_imag,
                            const float* __restrict__ C_re,
                            const float* __restrict__ C_im,
                            const float* __restrict__ out_w) {
    int idx = blockIdx.x * blockDim.x + threadIdx.x;
    if (idx < NLAY * 512 * HCH) {
        float w = out_w[idx];
        __nv_bfloat16 hi = __float2bfloat16(w);
        g_wh[idx] = hi;
        g_wl[idx] = __float2bfloat16(w - __bfloat162float(hi));
    }
    if (idx < NLAY * HCH * NST) {
        int layer = idx / (HCH * NST);
        int hn    = idx - layer * (HCH * NST);
        int h     = hn / NST;

        float dt  = expf(log_dt[layer * HCH + h]);
        float Are = -expf(log_A_real[idx]);
        float Aim = A_imag[idx];
        float dre = Are * dt;
        float dimg = Aim * dt;

        float sy, cy;
        sincosf(dimg, &sy, &cy);
        float em1 = expm1f(dre);
        float ex  = em1 + 1.0f;
        float wre = ex * cy;
        float wim = ex * sy;
        float emr = fmaf(em1, cy, cy - 1.0f);
        float emi = ex * sy;

        float inv = 1.0f / fmaf(Are, Are, Aim * Aim);
        float tre = fmaf(emr, Are, emi * Aim) * inv;
        float tim = fmaf(emi, Are, -emr * Aim) * inv;

        float cre = C_re[idx], cim = C_im[idx];
        float ctre = fmaf(cre, tre, -cim * tim);
        float ctim = fmaf(cre, tim, cim * tre);

        g_par[layer][0][hn] = wre;
        g_par[layer][1][hn] = wim;
        g_par[layer][2][hn] = 2.0f * ctre;
        g_par[layer][3][hn] = -2.0f * ctim;
    }
}

// ===========================================================================
// Encoder
// ===========================================================================
__global__ void __launch_bounds__(256) encoder_kernel(
    const float* __restrict__ x,
    const float* __restrict__ enc_w,
    const float* __restrict__ enc_b) {
    extern __shared__ float sm[];
    float* Wsh = sm;               // [64][256]
    float* Xsh = sm + 64 * HCH;    // [64][68]

    int b    = blockIdx.y;
    int pos0 = blockIdx.x * 64;
    int tid  = threadIdx.x;

    {
        const float4* wrow = (const float4*)(enc_w + (size_t)tid * DIN);
#pragma unroll
        for (int q = 0; q < 16; q++) {
            float4 v = wrow[q];
            Wsh[(q * 4 + 0) * HCH + tid] = v.x;
            Wsh[(q * 4 + 1) * HCH + tid] = v.y;
            Wsh[(q * 4 + 2) * HCH + tid] = v.z;
            Wsh[(q * 4 + 3) * HCH + tid] = v.w;
        }
    }
    {
#pragma unroll
        for (int k = 0; k < 4; k++) {
            int e  = tid + k * 256;
            int l  = e >> 4;
            int i4 = e & 15;
            const float4* xr =
                (const float4*)(x + ((size_t)(b * LSEQ) + pos0 + l) * DIN);
            float4 v = xr[i4];
            Xsh[(i4 * 4 + 0) * 68 + l] = v.x;
            Xsh[(i4 * 4 + 1) * 68 + l] = v.y;
            Xsh[(i4 * 4 + 2) * 68 + l] = v.z;
            Xsh[(i4 * 4 + 3) * 68 + l] = v.w;
        }
    }
    __syncthreads();

    int th = tid >> 3;
    int tl = tid & 7;
    ull acc2[8][4];
#pragma unroll
    for (int r = 0; r < 8; r++)
#pragma unroll
        for (int c = 0; c < 4; c++) acc2[r][c] = 0ULL;

    for (int i = 0; i < DIN; i++) {
        float4 a0 = *(const float4*)&Wsh[i * HCH + th * 8];
        float4 a1 = *(const float4*)&Wsh[i * HCH + th * 8 + 4];
        ulonglong2 b0 = *(const ulonglong2*)&Xsh[i * 68 + tl * 8];
        ulonglong2 b1 = *(const ulonglong2*)&Xsh[i * 68 + tl * 8 + 4];
        ull bv[4] = {b0.x, b0.y, b1.x, b1.y};
        float av[8] = {a0.x, a0.y, a0.z, a0.w, a1.x, a1.y, a1.z, a1.w};
#pragma unroll
        for (int r = 0; r < 8; r++) {
            ull ar = pack2(av[r], av[r]);
#pragma unroll
            for (int c = 0; c < 4; c++) fma2(acc2[r][c], ar, bv[c]);
        }
    }

#pragma unroll
    for (int r = 0; r < 8; r++) {
        int h = th * 8 + r;
        float bias = __ldg(&enc_b[h]);
        float* dst = g_h + ((size_t)(b * HCH + h)) * LSEQ + pos0 + tl * 8;
        float2 p0 = unpack2(acc2[r][0]);
        float2 p1 = unpack2(acc2[r][1]);
        float2 p2 = unpack2(acc2[r][2]);
        float2 p3 = unpack2(acc2[r][3]);
        float4 o0 = make_float4(p0.x + bias, p0.y + bias, p1.x + bias, p1.y + bias);
        float4 o1 = make_float4(p2.x + bias, p2.y + bias, p3.x + bias, p3.y + bias);
        ((float4*)dst)[0] = o0;
        ((float4*)dst)[1] = o1;
    }
}

// ===========================================================================
// SSM scan + D-skip + GELU -> bf16 hi/lo, [c][l] layout.
// R12 body verbatim (measured best: 231 us). Packed-pair variants regressed.
// ===========================================================================
__global__ void __launch_bounds__(128) scan_kernel(const float* __restrict__ Dvec,
                                                   int layer) {
    __shared__ float sh[4][32][36];
    int tid  = threadIdx.x;
    int wid  = tid >> 5;
    int lane = tid & 31;
    int c    = blockIdx.x * 4 + wid;
    int h    = c & (HCH - 1);

    const float* par = &g_par[layer][0][0];
    float wre = par[0 * (HCH * NST) + h * NST + lane];
    float wim = par[1 * (HCH * NST) + h * NST + lane];
    float ca  = par[2 * (HCH * NST) + h * NST + lane];
    float cb  = par[3 * (HCH * NST) + h * NST + lane];
    float Dh  = __ldg(&Dvec[layer * HCH + h]);

    const float* zin = g_h + (size_t)c * LSEQ;
    __nv_bfloat16* yh = g_yh + (size_t)c * LSEQ;
    __nv_bfloat16* yl = g_yl + (size_t)c * LSEQ;
    float (*S)[36] = sh[wid];

    float sre = 0.0f, sim = 0.0f;
    float zv = zin[lane];
    for (int l0 = 0; l0 < LSEQ; l0 += 32) {
        float zn = (l0 + 32 < LSEQ) ? zin[l0 + 32 + lane] : 0.0f;
#pragma unroll
        for (int t = 0; t < 32; t++) {
            float z  = __shfl_sync(0xffffffffu, zv, t);
            float nr = fmaf(wre, sre, z);
            nr       = fmaf(-wim, sim, nr);
            float ni = fmaf(wim, sre, wre * sim);
            sre = nr;
            sim = ni;
            S[t][lane] = fmaf(ca, sre, cb * sim);
        }
        __syncwarp();
        ull a0 = 0ULL, a1 = 0ULL, a2 = 0ULL, a3 = 0ULL;
        const float* row = &S[lane][0];
#pragma unroll
        for (int q = 0; q < 8; q += 2) {
            ulonglong2 p0 = *(const ulonglong2*)(row + q * 4);
            ulonglong2 p1 = *(const ulonglong2*)(row + q * 4 + 4);
            add2(a0, p0.x);
            add2(a1, p0.y);
            add2(a2, p1.x);
            add2(a3, p1.y);
        }
        add2(a0, a2);
        add2(a1, a3);
        add2(a0, a1);
        float2 fr = unpack2(a0);
        float acc = fr.x + fr.y;

        float yv = fmaf(Dh, zv, acc);
        float u  = 0.7978845608028654f * fmaf(0.044715f, yv * yv * yv, yv);
        float gv = yv / (1.0f + __expf(-2.0f * u));
        __nv_bfloat16 bh = __float2bfloat16(gv);
        __nv_bfloat16 bl = __float2bfloat16(gv - __bfloat162float(bh));
        yh[l0 + lane] = bh;
        yl[l0 + lane] = bl;
        __syncwarp();
        zv = zn;
    }
}

// ===========================================================================
// FUSED: HMMA GEMM (bf16 3-term split, fp32 acc) + bias + GLU + residual +
// channel LayerNorm. 512 threads / 16 warps. Mainloop chunk loop is FULLY
// UNROLLED so buf parity, k0 and all LDSM / cp.async offsets are
// compile-time (kills the 17% alu pipe spent on IMAD address math).
// ===========================================================================
#define FA_STRIDE 144
#define FA_TILE   (32 * FA_STRIDE)                 // 4608
#define FB_STRIDE 80
#define FB_TILE   (512 * FB_STRIDE)                // 40960
#define F_AH      0
#define F_AL      FA_TILE
#define F_BH      (2 * FA_TILE)
#define F_BL      (2 * FA_TILE + FB_TILE)
#define F_BUF     (2 * FA_TILE + 2 * FB_TILE)      // 91136
#define FUSED_SMEM (2 * F_BUF)                     // 182272
#define EPI_G2    0                                // f32 [64][260]
#define EPI_RES   (64 * 260 * 4)                   // f32 [64][260]

__global__ void __launch_bounds__(512, 1) fused_glu_ln_kernel(
    const float* __restrict__ out_b, const float* __restrict__ ln_w,
    const float* __restrict__ ln_b, int layer) {
    extern __shared__ char smem[];
    __shared__ float s_ob[512];
    __shared__ float s_lnw[HCH];
    __shared__ float s_lnb[HCH];
    __shared__ float s_mu[64];
    __shared__ float s_rs[64];

    int tid  = threadIdx.x;
    int wid  = tid >> 5;
    int lane = tid & 31;
    int row0 = blockIdx.x * 64;           // position rows, in [0, B*L)
    int b    = row0 >> 12;
    int pos0 = row0 & (LSEQ - 1);

    s_ob[tid] = __ldg(&out_b[layer * 512 + tid]);
    if (tid < HCH) {
        s_lnw[tid] = __ldg(&ln_w[layer * HCH + tid]);
        s_lnb[tid] = __ldg(&ln_b[layer * HCH + tid]);
    }

    const __nv_bfloat16* Ah = g_yh + ((size_t)(b * HCH)) * LSEQ + pos0;
    const __nv_bfloat16* Al = g_yl + ((size_t)(b * HCH)) * LSEQ + pos0;
    const __nv_bfloat16* Bh = g_wh + (size_t)layer * 512 * HCH;
    const __nv_bfloat16* Bl = g_wl + (size_t)layer * 512 * HCH;

    uint32_t sb = smem_u32(smem);

    int a_kr  = tid >> 3;        // only tid<256 used (k-row 0..31)
    int a_seg = tid & 7;
    int b_jr0 = tid >> 2;        // 0..127 (then +128*i)
    int b_seg = tid & 3;

    float acc[16][4];
#pragma unroll
    for (int t = 0; t < 16; t++)
#pragma unroll
        for (int e = 0; e < 4; e++) acc[t][e] = 0.0f;

    int mt = wid >> 2;           // 0..3 (16-row group)
    int jq = wid & 3;            // 0..3 (128-j quarter)

    // Precomputed (loop-invariant) address bases
    uint32_t a_stage = sb + a_kr * FA_STRIDE + a_seg * 16;          // + buf*F_BUF
    uint32_t b_stage = sb + b_jr0 * FB_STRIDE + b_seg * 16;         // + buf*F_BUF
    int f_kr = (lane & 7) + ((lane >> 4) << 3);
    int f_mc = ((lane >> 3) & 1) * 8;
    uint32_t a_frag = sb + f_kr * FA_STRIDE + (mt * 16 + f_mc) * 2; // + buf, ks, pass
    uint32_t b_frag = sb + (jq * 128 + (lane & 15)) * FB_STRIDE +
                      ((lane >> 4) * 16);                           // + buf, ks, ng, pass

    // stage chunk 0
    {
        if (tid < 256) {
            size_t go = (size_t)a_kr * LSEQ + a_seg * 8;
            cp16(a_stage + F_AH, Ah + go);
            cp16(a_stage + F_AL, Al + go);
        }
#pragma unroll
        for (int i = 0; i < 4; i++) {
            size_t go = (size_t)(b_jr0 + i * 128) * HCH + b_seg * 8;
            cp16(b_stage + i * 128 * FB_STRIDE + F_BH, Bh + go);
            cp16(b_stage + i * 128 * FB_STRIDE + F_BL, Bl + go);
        }
        CP_COMMIT();
    }

#pragma unroll
    for (int ch = 0; ch < 8; ch++) {
        const int buf = ch & 1;
        if (ch < 7) {
            const uint32_t soff = (buf ^ 1) * F_BUF;
            const int k0 = (ch + 1) * 32;
            if (tid < 256) {
                size_t go = (size_t)(k0 + a_kr) * LSEQ + a_seg * 8;
                cp16(a_stage + soff + F_AH, Ah + go);
                cp16(a_stage + soff + F_AL, Al + go);
            }
#pragma unroll
            for (int i = 0; i < 4; i++) {
                size_t go = (size_t)(b_jr0 + i * 128) * HCH + k0 + b_seg * 8;
                cp16(b_stage + soff + i * 128 * FB_STRIDE + F_BH, Bh + go);
                cp16(b_stage + soff + i * 128 * FB_STRIDE + F_BL, Bl + go);
            }
            CP_COMMIT();
            CP_WAIT1();
        } else {
            CP_WAIT0();
        }
        __syncthreads();

        const uint32_t aF = a_frag + buf * F_BUF;
        const uint32_t bF = b_frag + buf * F_BUF;
#pragma unroll
        for (int pass = 0; pass < 3; pass++) {
            const uint32_t aoff = aF + (pass == 2 ? F_AL : F_AH);
            const uint32_t boff = bF + (pass == 1 ? F_BL : F_BH);
#pragma unroll
            for (int ks = 0; ks < 2; ks++) {
                uint32_t afrag[4];
                ldsm4t(afrag, aoff + ks * 16 * FA_STRIDE);
#pragma unroll
                for (int grp = 0; grp < 2; grp++) {
                    uint32_t bfrag[4][4];
#pragma unroll
                    for (int gg = 0; gg < 4; gg++) {
                        int ng = grp * 4 + gg;
                        ldsm4(bfrag[gg], boff + ng * 16 * FB_STRIDE + ks * 32);
                    }
#pragma unroll
                    for (int gg = 0; gg < 4; gg++) {
                        int ng = grp * 4 + gg;
                        mma_bf16(acc[ng * 2],     afrag, bfrag[gg][0], bfrag[gg][2]);
                        mma_bf16(acc[ng * 2 + 1], afrag, bfrag[gg][1], bfrag[gg][3]);
                    }
                }
            }
        }
        __syncthreads();
    }

    // ---------------- fused epilogue (aliases tile smem) ----------------
    float* Gs2 = (float*)(smem + EPI_G2);    // [64][260]
    float* Rsm = (float*)(smem + EPI_RES);   // [64][260]

    {
        const float* resb = g_h + (size_t)(b * HCH) * LSEQ + pos0;
#pragma unroll
        for (int i = 0; i < 8; i++) {
            int flat = tid + i * 512;
            int h    = flat >> 4;
            int sg   = flat & 15;
            float4 v = *(const float4*)(resb + (size_t)h * LSEQ + sg * 4);
            Rsm[(sg * 4 + 0) * 260 + h] = v.x;
            Rsm[(sg * 4 + 1) * 260 + h] = v.y;
            Rsm[(sg * 4 + 2) * 260 + h] = v.z;
            Rsm[(sg * 4 + 3) * 260 + h] = v.w;
        }
    }
    if (jq >= 2) {
#pragma unroll
        for (int t = 0; t < 16; t++) {
            int j2 = (jq - 2) * 128 + (t >> 1) * 16 + (t & 1) * 8 + (lane & 3) * 2;
            int r  = mt * 16 + (lane >> 2);
            float bb0 = s_ob[256 + j2];
            float bb1 = s_ob[256 + j2 + 1];
            Gs2[r * 260 + j2]           = acc[t][0] + bb0;
            Gs2[r * 260 + j2 + 1]       = acc[t][1] + bb1;
            Gs2[(r + 8) * 260 + j2]     = acc[t][2] + bb0;
            Gs2[(r + 8) * 260 + j2 + 1] = acc[t][3] + bb1;
        }
    }
    __syncthreads();

    if (jq < 2) {
#pragma unroll
        for (int t = 0; t < 16; t++) {
            int h = jq * 128 + (t >> 1) * 16 + (t & 1) * 8 + (lane & 3) * 2;
            int r = mt * 16 + (lane >> 2);
            float bb0 = s_ob[h];
            float bb1 = s_ob[h + 1];
#pragma unroll
            for (int e = 0; e < 4; e++) {
                int rr = r + ((e >> 1) << 3);
                int hh = h + (e & 1);
                float g1 = acc[t][e] + ((e & 1) ? bb1 : bb0);
                float g2 = Gs2[rr * 260 + hh];
                float u  = fmaf(g1, 1.0f / (1.0f + __expf(-g2)),
                                Rsm[rr * 260 + hh]);
                Gs2[rr * 260 + hh] = u;
            }
        }
    }
    __syncthreads();

    {
        int r = tid >> 3;
        int q = tid & 7;
        float s = 0.0f, sq = 0.0f;
#pragma unroll
        for (int i = 0; i < 32; i++) {
            float v = Gs2[r * 260 + q * 32 + i];
            s += v;
            sq = fmaf(v, v, sq);
        }
        s  += __shfl_xor_sync(0xffffffffu, s, 1);
        sq += __shfl_xor_sync(0xffffffffu, sq, 1);
        s  += __shfl_xor_sync(0xffffffffu, s, 2);
        sq += __shfl_xor_sync(0xffffffffu, sq, 2);
        s  += __shfl_xor_sync(0xffffffffu, s, 4);
        sq += __shfl_xor_sync(0xffffffffu, sq, 4);
        if (q == 0) {
            float m = s * (1.0f / 256.0f);
            s_mu[r] = m;
            s_rs[r] = rsqrtf(fmaf(-m, m, sq * (1.0f / 256.0f)) + 1e-5f);
        }
    }
    __syncthreads();

    {
        int h    = tid & 255;
        int half = tid >> 8;
        float w  = s_lnw[h];
        float bb = s_lnb[h];
        float* outp = g_h + ((size_t)(b * HCH + h)) * LSEQ + pos0 + half * 32;
#pragma unroll
        for (int p4 = 0; p4 < 8; p4++) {
            int pp = half * 32 + p4 * 4;
            float4 o;
            float u0 = Gs2[(pp + 0) * 260 + h];
            float u1 = Gs2[(pp + 1) * 260 + h];
            float u2 = Gs2[(pp + 2) * 260 + h];
            float u3 = Gs2[(pp + 3) * 260 + h];
            o.x = fmaf((u0 - s_mu[pp + 0]) * s_rs[pp + 0], w, bb);
            o.y = fmaf((u1 - s_mu[pp + 1]) * s_rs[pp + 1], w, bb);
            o.z = fmaf((u2 - s_mu[pp + 2]) * s_rs[pp + 2], w, bb);
            o.w = fmaf((u3 - s_mu[pp + 3]) * s_rs[pp + 3], w, bb);
            *(float4*)(outp + p4 * 4) = o;
        }
    }
}

// ===========================================================================
// Decoder
// ===========================================================================
__global__ void __launch_bounds__(256) decoder_kernel(
    const float* __restrict__ dec_w, const float* __restrict__ dec_b,
    float* __restrict__ out) {
    __shared__ float wsh[DOUT * HCH];
    __shared__ float bsh[DOUT];
    int b    = blockIdx.y;
    int pos0 = blockIdx.x * 256;
    int tid  = threadIdx.x;
    for (int e = tid; e < DOUT * HCH; e += 256) wsh[e] = dec_w[e];
    if (tid < DOUT) bsh[tid] = dec_b[tid];
    __syncthreads();

    float acc[DOUT];
#pragma unroll
    for (int o = 0; o < DOUT; o++) acc[o] = bsh[o];

    const float* hp = g_h + (size_t)b * HCH * LSEQ + pos0 + tid;
    for (int h = 0; h < HCH; h++) {
        float xv = hp[(size_t)h * LSEQ];
#pragma unroll
        for (int o = 0; o < DOUT; o++)
            acc[o] = fmaf(xv, wsh[o * HCH + h], acc[o]);
    }
    float* op = out + ((size_t)(b * LSEQ) + pos0 + tid) * DOUT;
#pragma unroll
    for (int o = 0; o < DOUT; o++) op[o] = acc[o];
}

// ===========================================================================
extern "C" void kernel_launch(void* const* d_in, const int* in_sizes, int n_in,
                              void* d_out, int out_size) {
    const float* x          = (const float*)d_in[0];
    const float* enc_w      = (const float*)d_in[1];
    const float* enc_b      = (const float*)d_in[2];
    const float* log_dt     = (const float*)d_in[3];
    const float* log_A_real = (const float*)d_in[4];
    const float* A_imag     = (const float*)d_in[5];
    const float* C_re       = (const float*)d_in[6];
    const float* C_im       = (const float*)d_in[7];
    const float* Dv         = (const float*)d_in[8];
    const float* out_w      = (const float*)d_in[9];
    const float* out_b      = (const float*)d_in[10];
    const float* ln_w       = (const float*)d_in[11];
    const float* ln_b       = (const float*)d_in[12];
    const float* dec_w      = (const float*)d_in[13];
    const float* dec_b      = (const float*)d_in[14];
    float* out = (float*)d_out;

    size_t enc_smem = (size_t)(64 * HCH + 64 * 68) * sizeof(float);
    cudaFuncSetAttribute(encoder_kernel,
                         cudaFuncAttributeMaxDynamicSharedMemorySize,
                         (int)enc_smem);
    cudaFuncSetAttribute(fused_glu_ln_kernel,
                         cudaFuncAttributeMaxDynamicSharedMemorySize,
                         FUSED_SMEM);

    prep_kernel<<<(NLAY * 512 * HCH + 255) / 256, 256>>>(
        log_dt, log_A_real, A_imag, C_re, C_im, out_w);
    encoder_kernel<<<dim3(LSEQ / 64, NBATCH), 256, enc_smem>>>(x, enc_w, enc_b);
    for (int layer = 0; layer < NLAY; layer++) {
        scan_kernel<<<1024, 128>>>(Dv, layer);
        fused_glu_ln_kernel<<<NBATCH * LSEQ / 64, 512, FUSED_SMEM>>>(
            out_b, ln_w, ln_b, layer);
    }
    decoder_kernel<<<dim3(LSEQ / 256, NBATCH), 256>>>(dec_w, dec_b, out);
}

// round 16
// speedup vs baseline: 1.1569x; 1.0464x over previous
#include <cuda_runtime.h>
#include <cuda_bf16.h>
#include <math.h>
#include <stdint.h>

#define NBATCH 16
#define LSEQ   4096
#define DIN    64
#define HCH    256
#define NST    32
#define NLAY   4
#define DOUT   10

typedef unsigned long long ull;

// ===========================================================================
// Base-ISA PTX helpers (compute_103 base — no tcgen05 / 'a'-suffix features)
// ===========================================================================
__device__ __forceinline__ uint32_t smem_u32(const void* p) {
    uint32_t a;
    asm("{ .reg .u64 t; cvta.to.shared.u64 t, %1; cvt.u32.u64 %0, t; }"
        : "=r"(a) : "l"(p));
    return a;
}
__device__ __forceinline__ void cp16(uint32_t dst, const void* src) {
    asm volatile("cp.async.cg.shared.global [%0], [%1], 16;"
                 :: "r"(dst), "l"(src));
}
#define CP_COMMIT() asm volatile("cp.async.commit_group;" ::: "memory")
#define CP_WAIT0()  asm volatile("cp.async.wait_group 0;" ::: "memory")
#define CP_WAIT1()  asm volatile("cp.async.wait_group 1;" ::: "memory")

__device__ __forceinline__ void ldsm4(uint32_t* r, uint32_t addr) {
    asm volatile("ldmatrix.sync.aligned.m8n8.x4.shared.b16 {%0,%1,%2,%3}, [%4];"
                 : "=r"(r[0]), "=r"(r[1]), "=r"(r[2]), "=r"(r[3]) : "r"(addr));
}
__device__ __forceinline__ void ldsm4t(uint32_t* r, uint32_t addr) {
    asm volatile("ldmatrix.sync.aligned.m8n8.x4.trans.shared.b16 {%0,%1,%2,%3}, [%4];"
                 : "=r"(r[0]), "=r"(r[1]), "=r"(r[2]), "=r"(r[3]) : "r"(addr));
}
__device__ __forceinline__ void mma_bf16(float* d, const uint32_t* a,
                                         uint32_t b0, uint32_t b1) {
    asm volatile(
        "mma.sync.aligned.m16n8k16.row.col.f32.bf16.bf16.f32 "
        "{%0,%1,%2,%3}, {%4,%5,%6,%7}, {%8,%9}, {%0,%1,%2,%3};"
        : "+f"(d[0]), "+f"(d[1]), "+f"(d[2]), "+f"(d[3])
        : "r"(a[0]), "r"(a[1]), "r"(a[2]), "r"(a[3]), "r"(b0), "r"(b1));
}

// ===========================================================================
// Packed fp32x2 helpers
// ===========================================================================
__device__ __forceinline__ ull pack2(float x, float y) {
    ull r;
    asm("mov.b64 %0, {%1, %2};" : "=l"(r) : "f"(x), "f"(y));
    return r;
}
__device__ __forceinline__ void fma2(ull& d, ull a, ull b) {
    asm("fma.rn.f32x2 %0, %1, %2, %0;" : "+l"(d) : "l"(a), "l"(b));
}
__device__ __forceinline__ void add2(ull& d, ull a) {
    asm("add.rn.f32x2 %0, %0, %1;" : "+l"(d) : "l"(a));
}
__device__ __forceinline__ float2 unpack2(ull v) {
    float2 r;
    asm("mov.b64 {%0, %1}, %2;" : "=f"(r.x), "=f"(r.y) : "l"(v));
    return r;
}

// ===========================================================================
// Device scratch
// ===========================================================================
__device__ float g_h[NBATCH * HCH * LSEQ];                       // (B,H,L)
__device__ __nv_bfloat16 g_yh[(size_t)NBATCH * HCH * LSEQ];      // y hi, [c][l]
__device__ __nv_bfloat16 g_yl[(size_t)NBATCH * HCH * LSEQ];      // y lo, [c][l]
__device__ __nv_bfloat16 g_wh[NLAY * 512 * HCH];                 // out_w hi
__device__ __nv_bfloat16 g_wl[NLAY * 512 * HCH];                 // out_w lo
__device__ float g_par[NLAY][4][HCH * NST];

// ===========================================================================
// Prep: SSM parameter precompute + out_w bf16 hi/lo split (merged).
// ===========================================================================
__global__ void prep_kernel(const float* __restrict__ log_dt,
                            const float* __restrict__ log_A_real,
                            const float* __restrict__ A_imag,
                            const float* __restrict__ C_re,
                            const float* __restrict__ C_im,
                            const float* __restrict__ out_w) {
    int idx = blockIdx.x * blockDim.x + threadIdx.x;
    if (idx < NLAY * 512 * HCH) {
        float w = out_w[idx];
        __nv_bfloat16 hi = __float2bfloat16(w);
        g_wh[idx] = hi;
        g_wl[idx] = __float2bfloat16(w - __bfloat162float(hi));
    }
    if (idx < NLAY * HCH * NST) {
        int layer = idx / (HCH * NST);
        int hn    = idx - layer * (HCH * NST);
        int h     = hn / NST;

        float dt  = expf(log_dt[layer * HCH + h]);
        float Are = -expf(log_A_real[idx]);
        float Aim = A_imag[idx];
        float dre = Are * dt;
        float dimg = Aim * dt;

        float sy, cy;
        sincosf(dimg, &sy, &cy);
        float em1 = expm1f(dre);
        float ex  = em1 + 1.0f;
        float wre = ex * cy;
        float wim = ex * sy;
        float emr = fmaf(em1, cy, cy - 1.0f);
        float emi = ex * sy;

        float inv = 1.0f / fmaf(Are, Are, Aim * Aim);
        float tre = fmaf(emr, Are, emi * Aim) * inv;
        float tim = fmaf(emi, Are, -emr * Aim) * inv;

        float cre = C_re[idx], cim = C_im[idx];
        float ctre = fmaf(cre, tre, -cim * tim);
        float ctim = fmaf(cre, tim, cim * tre);

        g_par[layer][0][hn] = wre;
        g_par[layer][1][hn] = wim;
        g_par[layer][2][hn] = 2.0f * ctre;
        g_par[layer][3][hn] = -2.0f * ctim;
    }
}

// ===========================================================================
// Encoder
// ===========================================================================
__global__ void __launch_bounds__(256) encoder_kernel(
    const float* __restrict__ x,
    const float* __restrict__ enc_w,
    const float* __restrict__ enc_b) {
    extern __shared__ float sm[];
    float* Wsh = sm;               // [64][256]
    float* Xsh = sm + 64 * HCH;    // [64][68]

    int b    = blockIdx.y;
    int pos0 = blockIdx.x * 64;
    int tid  = threadIdx.x;

    {
        const float4* wrow = (const float4*)(enc_w + (size_t)tid * DIN);
#pragma unroll
        for (int q = 0; q < 16; q++) {
            float4 v = wrow[q];
            Wsh[(q * 4 + 0) * HCH + tid] = v.x;
            Wsh[(q * 4 + 1) * HCH + tid] = v.y;
            Wsh[(q * 4 + 2) * HCH + tid] = v.z;
            Wsh[(q * 4 + 3) * HCH + tid] = v.w;
        }
    }
    {
#pragma unroll
        for (int k = 0; k < 4; k++) {
            int e  = tid + k * 256;
            int l  = e >> 4;
            int i4 = e & 15;
            const float4* xr =
                (const float4*)(x + ((size_t)(b * LSEQ) + pos0 + l) * DIN);
            float4 v = xr[i4];
            Xsh[(i4 * 4 + 0) * 68 + l] = v.x;
            Xsh[(i4 * 4 + 1) * 68 + l] = v.y;
            Xsh[(i4 * 4 + 2) * 68 + l] = v.z;
            Xsh[(i4 * 4 + 3) * 68 + l] = v.w;
        }
    }
    __syncthreads();

    int th = tid >> 3;
    int tl = tid & 7;
    ull acc2[8][4];
#pragma unroll
    for (int r = 0; r < 8; r++)
#pragma unroll
        for (int c = 0; c < 4; c++) acc2[r][c] = 0ULL;

    for (int i = 0; i < DIN; i++) {
        float4 a0 = *(const float4*)&Wsh[i * HCH + th * 8];
        float4 a1 = *(const float4*)&Wsh[i * HCH + th * 8 + 4];
        ulonglong2 b0 = *(const ulonglong2*)&Xsh[i * 68 + tl * 8];
        ulonglong2 b1 = *(const ulonglong2*)&Xsh[i * 68 + tl * 8 + 4];
        ull bv[4] = {b0.x, b0.y, b1.x, b1.y};
        float av[8] = {a0.x, a0.y, a0.z, a0.w, a1.x, a1.y, a1.z, a1.w};
#pragma unroll
        for (int r = 0; r < 8; r++) {
            ull ar = pack2(av[r], av[r]);
#pragma unroll
            for (int c = 0; c < 4; c++) fma2(acc2[r][c], ar, bv[c]);
        }
    }

#pragma unroll
    for (int r = 0; r < 8; r++) {
        int h = th * 8 + r;
        float bias = __ldg(&enc_b[h]);
        float* dst = g_h + ((size_t)(b * HCH + h)) * LSEQ + pos0 + tl * 8;
        float2 p0 = unpack2(acc2[r][0]);
        float2 p1 = unpack2(acc2[r][1]);
        float2 p2 = unpack2(acc2[r][2]);
        float2 p3 = unpack2(acc2[r][3]);
        float4 o0 = make_float4(p0.x + bias, p0.y + bias, p1.x + bias, p1.y + bias);
        float4 o1 = make_float4(p2.x + bias, p2.y + bias, p3.x + bias, p3.y + bias);
        ((float4*)dst)[0] = o0;
        ((float4*)dst)[1] = o1;
    }
}

// ===========================================================================
// SSM scan + D-skip + GELU -> bf16 hi/lo, [c][l] layout. (R12 body verbatim)
// ===========================================================================
__global__ void __launch_bounds__(128) scan_kernel(const float* __restrict__ Dvec,
                                                   int layer) {
    __shared__ float sh[4][32][36];
    int tid  = threadIdx.x;
    int wid  = tid >> 5;
    int lane = tid & 31;
    int c    = blockIdx.x * 4 + wid;
    int h    = c & (HCH - 1);

    const float* par = &g_par[layer][0][0];
    float wre = par[0 * (HCH * NST) + h * NST + lane];
    float wim = par[1 * (HCH * NST) + h * NST + lane];
    float ca  = par[2 * (HCH * NST) + h * NST + lane];
    float cb  = par[3 * (HCH * NST) + h * NST + lane];
    float Dh  = __ldg(&Dvec[layer * HCH + h]);

    const float* zin = g_h + (size_t)c * LSEQ;
    __nv_bfloat16* yh = g_yh + (size_t)c * LSEQ;
    __nv_bfloat16* yl = g_yl + (size_t)c * LSEQ;
    float (*S)[36] = sh[wid];

    float sre = 0.0f, sim = 0.0f;
    float zv = zin[lane];
    for (int l0 = 0; l0 < LSEQ; l0 += 32) {
        float zn = (l0 + 32 < LSEQ) ? zin[l0 + 32 + lane] : 0.0f;
#pragma unroll
        for (int t = 0; t < 32; t++) {
            float z  = __shfl_sync(0xffffffffu, zv, t);
            float nr = fmaf(wre, sre, z);
            nr       = fmaf(-wim, sim, nr);
            float ni = fmaf(wim, sre, wre * sim);
            sre = nr;
            sim = ni;
            S[t][lane] = fmaf(ca, sre, cb * sim);
        }
        __syncwarp();
        ull a0 = 0ULL, a1 = 0ULL, a2 = 0ULL, a3 = 0ULL;
        const float* row = &S[lane][0];
#pragma unroll
        for (int q = 0; q < 8; q += 2) {
            ulonglong2 p0 = *(const ulonglong2*)(row + q * 4);
            ulonglong2 p1 = *(const ulonglong2*)(row + q * 4 + 4);
            add2(a0, p0.x);
            add2(a1, p0.y);
            add2(a2, p1.x);
            add2(a3, p1.y);
        }
        add2(a0, a2);
        add2(a1, a3);
        add2(a0, a1);
        float2 fr = unpack2(a0);
        float acc = fr.x + fr.y;

        float yv = fmaf(Dh, zv, acc);
        float u  = 0.7978845608028654f * fmaf(0.044715f, yv * yv * yv, yv);
        float gv = yv / (1.0f + __expf(-2.0f * u));
        __nv_bfloat16 bh = __float2bfloat16(gv);
        __nv_bfloat16 bl = __float2bfloat16(gv - __bfloat162float(bh));
        yh[l0 + lane] = bh;
        yl[l0 + lane] = bl;
        __syncwarp();
        zv = zn;
    }
}

// ===========================================================================
// FUSED: HMMA GEMM (bf16 3-term split, fp32 acc) + bias + GLU + residual +
// channel LayerNorm. 512 threads / 16 warps; R12 structure (rolled chunk
// loop) but warp tile remapped to 32 rows x 64 j:
//   warp = (mp = wid>>3 [32-row half], jo = wid&7 [64-j octant]).
// Each B fragment now feeds 4 MMAs (2 m-tiles) -> LDSM/warp/chunk 54 -> 36.
// acc tile t = mt2*8 + nt:  rows mp*32 + mt2*16, j = jo*64 + nt*8.
// ===========================================================================
#define FA_STRIDE 144
#define FA_TILE   (32 * FA_STRIDE)                 // 4608
#define FB_STRIDE 80
#define FB_TILE   (512 * FB_STRIDE)                // 40960
#define F_AH      0
#define F_AL      FA_TILE
#define F_BH      (2 * FA_TILE)
#define F_BL      (2 * FA_TILE + FB_TILE)
#define F_BUF     (2 * FA_TILE + 2 * FB_TILE)      // 91136
#define FUSED_SMEM (2 * F_BUF)                     // 182272
#define EPI_G2    0                                // f32 [64][260]
#define EPI_RES   (64 * 260 * 4)                   // f32 [64][260]

__global__ void __launch_bounds__(512, 1) fused_glu_ln_kernel(
    const float* __restrict__ out_b, const float* __restrict__ ln_w,
    const float* __restrict__ ln_b, int layer) {
    extern __shared__ char smem[];
    __shared__ float s_ob[512];
    __shared__ float s_lnw[HCH];
    __shared__ float s_lnb[HCH];
    __shared__ float s_mu[64];
    __shared__ float s_rs[64];

    int tid  = threadIdx.x;
    int wid  = tid >> 5;
    int lane = tid & 31;
    int row0 = blockIdx.x * 64;           // position rows, in [0, B*L)
    int b    = row0 >> 12;
    int pos0 = row0 & (LSEQ - 1);

    s_ob[tid] = __ldg(&out_b[layer * 512 + tid]);
    if (tid < HCH) {
        s_lnw[tid] = __ldg(&ln_w[layer * HCH + tid]);
        s_lnb[tid] = __ldg(&ln_b[layer * HCH + tid]);
    }

    const __nv_bfloat16* Ah = g_yh + ((size_t)(b * HCH)) * LSEQ + pos0;
    const __nv_bfloat16* Al = g_yl + ((size_t)(b * HCH)) * LSEQ + pos0;
    const __nv_bfloat16* Bh = g_wh + (size_t)layer * 512 * HCH;
    const __nv_bfloat16* Bl = g_wl + (size_t)layer * 512 * HCH;

    uint32_t sb = smem_u32(smem);

    int a_kr  = tid >> 3;        // only tid<256 used (k-row 0..31)
    int a_seg = tid & 7;
    int b_jr0 = tid >> 2;        // 0..127 (then +128*i)
    int b_seg = tid & 3;

    float acc[16][4];
#pragma unroll
    for (int t = 0; t < 16; t++)
#pragma unroll
        for (int e = 0; e < 4; e++) acc[t][e] = 0.0f;

    int mp = wid >> 3;           // 0..1 (32-row half)
    int jo = wid & 7;            // 0..7 (64-j octant)

    // stage chunk 0
    {
        uint32_t base = sb;
        if (tid < 256) {
            uint32_t d = base + a_kr * FA_STRIDE + a_seg * 16;
            size_t go = (size_t)a_kr * LSEQ + a_seg * 8;
            cp16(d + F_AH, Ah + go);
            cp16(d + F_AL, Al + go);
        }
#pragma unroll
        for (int i = 0; i < 4; i++) {
            int jr = b_jr0 + i * 128;
            uint32_t d = base + jr * FB_STRIDE + b_seg * 16;
            size_t go = (size_t)jr * HCH + b_seg * 8;
            cp16(d + F_BH, Bh + go);
            cp16(d + F_BL, Bl + go);
        }
        CP_COMMIT();
    }

    int f_kr = (lane & 7) + ((lane >> 4) << 3);
    int f_mc = ((lane >> 3) & 1) * 8;

    int buf = 0;
    for (int ch = 0; ch < 8; ch++) {
        if (ch < 7) {
            uint32_t base = sb + (buf ^ 1) * F_BUF;
            int k0 = (ch + 1) * 32;
            if (tid < 256) {
                uint32_t d = base + a_kr * FA_STRIDE + a_seg * 16;
                size_t go = (size_t)(k0 + a_kr) * LSEQ + a_seg * 8;
                cp16(d + F_AH, Ah + go);
                cp16(d + F_AL, Al + go);
            }
#pragma unroll
            for (int i = 0; i < 4; i++) {
                int jr = b_jr0 + i * 128;
                uint32_t d = base + jr * FB_STRIDE + b_seg * 16;
                size_t go = (size_t)jr * HCH + k0 + b_seg * 8;
                cp16(d + F_BH, Bh + go);
                cp16(d + F_BL, Bl + go);
            }
            CP_COMMIT();
            CP_WAIT1();
        } else {
            CP_WAIT0();
        }
        __syncthreads();

        uint32_t cbase = sb + buf * F_BUF;
#pragma unroll
        for (int pass = 0; pass < 3; pass++) {
            uint32_t aoff = cbase + (pass == 2 ? F_AL : F_AH);
            uint32_t boff = cbase + (pass == 1 ? F_BL : F_BH);
#pragma unroll
            for (int ks = 0; ks < 2; ks++) {
                uint32_t arow = aoff + (ks * 16 + f_kr) * FA_STRIDE;
                uint32_t af0[4], af1[4];
                ldsm4t(af0, arow + (mp * 32 + f_mc) * 2);
                ldsm4t(af1, arow + (mp * 32 + 16 + f_mc) * 2);
#pragma unroll
                for (int ng = 0; ng < 4; ng++) {
                    uint32_t bfrag[4];
                    uint32_t ba = boff +
                        (jo * 64 + ng * 16 + (lane & 15)) * FB_STRIDE +
                        ks * 32 + (lane >> 4) * 16;
                    ldsm4(bfrag, ba);
                    mma_bf16(acc[ng * 2],         af0, bfrag[0], bfrag[2]);
                    mma_bf16(acc[ng * 2 + 1],     af0, bfrag[1], bfrag[3]);
                    mma_bf16(acc[8 + ng * 2],     af1, bfrag[0], bfrag[2]);
                    mma_bf16(acc[8 + ng * 2 + 1], af1, bfrag[1], bfrag[3]);
                }
            }
        }
        __syncthreads();
        buf ^= 1;
    }

    // ---------------- fused epilogue (aliases tile smem) ----------------
    float* Gs2 = (float*)(smem + EPI_G2);    // [64][260]
    float* Rsm = (float*)(smem + EPI_RES);   // [64][260]

    {
        const float* resb = g_h + (size_t)(b * HCH) * LSEQ + pos0;
#pragma unroll
        for (int i = 0; i < 8; i++) {
            int flat = tid + i * 512;
            int h    = flat >> 4;
            int sg   = flat & 15;
            float4 v = *(const float4*)(resb + (size_t)h * LSEQ + sg * 4);
            Rsm[(sg * 4 + 0) * 260 + h] = v.x;
            Rsm[(sg * 4 + 1) * 260 + h] = v.y;
            Rsm[(sg * 4 + 2) * 260 + h] = v.z;
            Rsm[(sg * 4 + 3) * 260 + h] = v.w;
        }
    }
    // jo>=4 warps: write g2 + bias into Gs2 (j 256..511)
    if (jo >= 4) {
#pragma unroll
        for (int t = 0; t < 16; t++) {
            int j2 = (jo - 4) * 64 + (t & 7) * 8 + (lane & 3) * 2;
            int r  = mp * 32 + (t >> 3) * 16 + (lane >> 2);
            float bb0 = s_ob[256 + j2];
            float bb1 = s_ob[256 + j2 + 1];
            Gs2[r * 260 + j2]           = acc[t][0] + bb0;
            Gs2[r * 260 + j2 + 1]       = acc[t][1] + bb1;
            Gs2[(r + 8) * 260 + j2]     = acc[t][2] + bb0;
            Gs2[(r + 8) * 260 + j2 + 1] = acc[t][3] + bb1;
        }
    }
    __syncthreads();

    // jo<4 warps: u = (g1+b1)*sigmoid(g2) + res, in place in Gs2 (h 0..255)
    if (jo < 4) {
#pragma unroll
        for (int t = 0; t < 16; t++) {
            int h = jo * 64 + (t & 7) * 8 + (lane & 3) * 2;
            int r = mp * 32 + (t >> 3) * 16 + (lane >> 2);
            float bb0 = s_ob[h];
            float bb1 = s_ob[h + 1];
#pragma unroll
            for (int e = 0; e < 4; e++) {
                int rr = r + ((e >> 1) << 3);
                int hh = h + (e & 1);
                float g1 = acc[t][e] + ((e & 1) ? bb1 : bb0);
                float g2 = Gs2[rr * 260 + hh];
                float u  = fmaf(g1, 1.0f / (1.0f + __expf(-g2)),
                                Rsm[rr * 260 + hh]);
                Gs2[rr * 260 + hh] = u;
            }
        }
    }
    __syncthreads();

    {
        int r = tid >> 3;
        int q = tid & 7;
        float s = 0.0f, sq = 0.0f;
#pragma unroll
        for (int i = 0; i < 32; i++) {
            float v = Gs2[r * 260 + q * 32 + i];
            s += v;
            sq = fmaf(v, v, sq);
        }
        s  += __shfl_xor_sync(0xffffffffu, s, 1);
        sq += __shfl_xor_sync(0xffffffffu, sq, 1);
        s  += __shfl_xor_sync(0xffffffffu, s, 2);
        sq += __shfl_xor_sync(0xffffffffu, sq, 2);
        s  += __shfl_xor_sync(0xffffffffu, s, 4);
        sq += __shfl_xor_sync(0xffffffffu, sq, 4);
        if (q == 0) {
            float m = s * (1.0f / 256.0f);
            s_mu[r] = m;
            s_rs[r] = rsqrtf(fmaf(-m, m, sq * (1.0f / 256.0f)) + 1e-5f);
        }
    }
    __syncthreads();

    {
        int h    = tid & 255;
        int half = tid >> 8;
        float w  = s_lnw[h];
        float bb = s_lnb[h];
        float* outp = g_h + ((size_t)(b * HCH + h)) * LSEQ + pos0 + half * 32;
#pragma unroll
        for (int p4 = 0; p4 < 8; p4++) {
            int pp = half * 32 + p4 * 4;
            float4 o;
            float u0 = Gs2[(pp + 0) * 260 + h];
            float u1 = Gs2[(pp + 1) * 260 + h];
            float u2 = Gs2[(pp + 2) * 260 + h];
            float u3 = Gs2[(pp + 3) * 260 + h];
            o.x = fmaf((u0 - s_mu[pp + 0]) * s_rs[pp + 0], w, bb);
            o.y = fmaf((u1 - s_mu[pp + 1]) * s_rs[pp + 1], w, bb);
            o.z = fmaf((u2 - s_mu[pp + 2]) * s_rs[pp + 2], w, bb);
            o.w = fmaf((u3 - s_mu[pp + 3]) * s_rs[pp + 3], w, bb);
            *(float4*)(outp + p4 * 4) = o;
        }
    }
}

// ===========================================================================
// Decoder
// ===========================================================================
__global__ void __launch_bounds__(256) decoder_kernel(
    const float* __restrict__ dec_w, const float* __restrict__ dec_b,
    float* __restrict__ out) {
    __shared__ float wsh[DOUT * HCH];
    __shared__ float bsh[DOUT];
    int b    = blockIdx.y;
    int pos0 = blockIdx.x * 256;
    int tid  = threadIdx.x;
    for (int e = tid; e < DOUT * HCH; e += 256) wsh[e] = dec_w[e];
    if (tid < DOUT) bsh[tid] = dec_b[tid];
    __syncthreads();

    float acc[DOUT];
#pragma unroll
    for (int o = 0; o < DOUT; o++) acc[o] = bsh[o];

    const float* hp = g_h + (size_t)b * HCH * LSEQ + pos0 + tid;
    for (int h = 0; h < HCH; h++) {
        float xv = hp[(size_t)h * LSEQ];
#pragma unroll
        for (int o = 0; o < DOUT; o++)
            acc[o] = fmaf(xv, wsh[o * HCH + h], acc[o]);
    }
    float* op = out + ((size_t)(b * LSEQ) + pos0 + tid) * DOUT;
#pragma unroll
    for (int o = 0; o < DOUT; o++) op[o] = acc[o];
}

// ===========================================================================
extern "C" void kernel_launch(void* const* d_in, const int* in_sizes, int n_in,
                              void* d_out, int out_size) {
    const float* x          = (const float*)d_in[0];
    const float* enc_w      = (const float*)d_in[1];
    const float* enc_b      = (const float*)d_in[2];
    const float* log_dt     = (const float*)d_in[3];
    const float* log_A_real = (const float*)d_in[4];
    const float* A_imag     = (const float*)d_in[5];
    const float* C_re       = (const float*)d_in[6];
    const float* C_im       = (const float*)d_in[7];
    const float* Dv         = (const float*)d_in[8];
    const float* out_w      = (const float*)d_in[9];
    const float* out_b      = (const float*)d_in[10];
    const float* ln_w       = (const float*)d_in[11];
    const float* ln_b       = (const float*)d_in[12];
    const float* dec_w      = (const float*)d_in[13];
    const float* dec_b      = (const float*)d_in[14];
    float* out = (float*)d_out;

    size_t enc_smem = (size_t)(64 * HCH + 64 * 68) * sizeof(float);
    cudaFuncSetAttribute(encoder_kernel,
                         cudaFuncAttributeMaxDynamicSharedMemorySize,
                         (int)enc_smem);
    cudaFuncSetAttribute(fused_glu_ln_kernel,
                         cudaFuncAttributeMaxDynamicSharedMemorySize,
                         FUSED_SMEM);

    prep_kernel<<<(NLAY * 512 * HCH + 255) / 256, 256>>>(
        log_dt, log_A_real, A_imag, C_re, C_im, out_w);
    encoder_kernel<<<dim3(LSEQ / 64, NBATCH), 256, enc_smem>>>(x, enc_w, enc_b);
    for (int layer = 0; layer < NLAY; layer++) {
        scan_kernel<<<1024, 128>>>(Dv, layer);
        fused_glu_ln_kernel<<<NBATCH * LSEQ / 64, 512, FUSED_SMEM>>>(
            out_b, ln_w, ln_b, layer);
    }
    decoder_kernel<<<dim3(LSEQ / 256, NBATCH), 256>>>(dec_w, dec_b, out);
}